// round 14
// baseline (speedup 1.0000x reference)
#include <cuda_runtime.h>
#include <cuda_bf16.h>
#include <cstdint>

// ---------------------------------------------------------------------------
// Arch gate: tcgen05 is sm_103a-ONLY (plain compute_103 phase must compile).
// ---------------------------------------------------------------------------
#if defined(__CUDA_ARCH__) && (__CUDA_ARCH__ == 1030) && defined(__CUDA_ARCH_FEAT_SM103_ALL)
#define TC_OK 1
#else
#define TC_OK 0
#endif

// ---------------------------------------------------------------------------
// Problem constants
// ---------------------------------------------------------------------------
#define N_EXPERTS 30
#define IN_SZ     1024
#define HID       2048
#define BATCH_SZ  8192

#define N_CLUSTERS 74            // 148 CTAs / 2
#define N_WORK     960           // 30 experts * 32 m-blocks of 256

// Exact power-of-2 operand scaling (folded out in epilogue)
#define X_SCALE   64.0f          // 2^6:  |x|max ~5.4 -> ~350 < 448
#define W_SCALE   8192.0f        // 2^13: |w|max 1/32 -> 256 < 448
#define INV_SCALE 1.9073486328125e-6f   // 2^-19 exact

// ---------------------------------------------------------------------------
// Device scratch (fp8 e4m3 blobs, SW128-swizzled SMEM images).
// g_xa: A blob(mb128, kc8) = 16KB: x rows [mb*128,+128), k [kc*128,+128).
//       kc-contiguous -> one m-block's full A = 128KB contiguous.
// g_wb: B blob(e, tile16, rank, kc8) = 8KB: 64 n-rows x 128B where
//       hid = tile*128 + rank*64 + row, k [kc*128,+128).
// ---------------------------------------------------------------------------
__device__ __align__(16) uint8_t g_xa[(size_t)BATCH_SZ * IN_SZ];                 // 8 MB
__device__ __align__(16) uint8_t g_wb[(size_t)N_EXPERTS * HID * IN_SZ];          // 63 MB
__device__ float g_zbuf[(size_t)N_EXPERTS * BATCH_SZ];                            // 1 MB

// ---------------------------------------------------------------------------
// PTX helpers
// ---------------------------------------------------------------------------
__device__ __forceinline__ uint32_t smem_to_u32(const void* p) {
    uint32_t a;
    asm("{ .reg .u64 t; cvta.to.shared.u64 t, %1; cvt.u32.u64 %0, t; }"
        : "=r"(a) : "l"(p));
    return a;
}

__device__ __forceinline__ uint32_t elect_one_pred() {
    uint32_t pred;
    asm volatile(
        "{\n\t.reg .pred p;\n\telect.sync _|p, 0xFFFFFFFF;\n\tselp.b32 %0, 1, 0, p;\n\t}"
        : "=r"(pred));
    return pred;
}

__device__ __forceinline__ uint32_t cluster_rank() {
    uint32_t r;
    asm("mov.u32 %0, %%cluster_ctarank;" : "=r"(r));
    return r;
}

#define MBARRIER_INIT(addr, cnt) \
    asm volatile("mbarrier.init.shared.b64 [%0], %1;" :: "r"((uint32_t)(addr)), "r"((uint32_t)(cnt)) : "memory")

#define MBARRIER_EXPECT_TX(addr, bytes) \
    asm volatile("mbarrier.arrive.expect_tx.shared.b64 _, [%0], %1;" \
        :: "r"((uint32_t)(addr)), "r"((uint32_t)(bytes)) : "memory")

// local wait, acquire at cta scope
#define MBARRIER_WAIT_PARITY(mbar_smem_addr, phase_parity) do { \
    uint32_t _mbar = (uint32_t)(mbar_smem_addr); \
    uint32_t _parity = (uint32_t)(phase_parity); \
    uint32_t _done; \
    asm volatile( \
        "{\n\t.reg .pred p;\n\t" \
        "mbarrier.try_wait.parity.acquire.cta.shared::cta.b64 p, [%1], %2;\n\t" \
        "selp.b32 %0, 1, 0, p;\n\t}" \
        : "=r"(_done) : "r"(_mbar), "r"(_parity) : "memory"); \
    if (!_done) { \
        asm volatile( \
            "{\n\t.reg .pred P1;\n\t" \
            "WAIT_LOOP_%=:\n\t" \
            "mbarrier.try_wait.parity.acquire.cta.shared::cta.b64 P1, [%0], %1, 0x989680;\n\t" \
            "@P1 bra.uni WAIT_DONE_%=;\n\t" \
            "bra.uni WAIT_LOOP_%=;\n\t" \
            "WAIT_DONE_%=:\n\t}" \
            :: "r"(_mbar), "r"(_parity) : "memory"); \
    } \
} while (0)

// cluster-scope acquire wait (peer-signaled barriers / peer data)
#define MBARRIER_WAIT_PARITY_CLU(mbar_smem_addr, phase_parity) do { \
    uint32_t _mbar = (uint32_t)(mbar_smem_addr); \
    uint32_t _parity = (uint32_t)(phase_parity); \
    uint32_t _done; \
    asm volatile( \
        "{\n\t.reg .pred p;\n\t" \
        "mbarrier.try_wait.parity.acquire.cluster.shared::cta.b64 p, [%1], %2;\n\t" \
        "selp.b32 %0, 1, 0, p;\n\t}" \
        : "=r"(_done) : "r"(_mbar), "r"(_parity) : "memory"); \
    if (!_done) { \
        asm volatile( \
            "{\n\t.reg .pred P1;\n\t" \
            "WAIT_LOOP_%=:\n\t" \
            "mbarrier.try_wait.parity.acquire.cluster.shared::cta.b64 P1, [%0], %1, 0x989680;\n\t" \
            "@P1 bra.uni WAIT_DONE_%=;\n\t" \
            "bra.uni WAIT_LOOP_%=;\n\t" \
            "WAIT_DONE_%=:\n\t}" \
            :: "r"(_mbar), "r"(_parity) : "memory"); \
    } \
} while (0)

// arrive on the same-offset mbarrier in cluster rank 0
#define MBARRIER_ARRIVE_RANK0(local_mbar_addr) \
    asm volatile( \
        "{\n\t.reg .b32 remAddr32;\n\t" \
        "mapa.shared::cluster.u32 remAddr32, %0, 0;\n\t" \
        "mbarrier.arrive.shared::cluster.b64 _, [remAddr32];\n\t}" \
        :: "r"((uint32_t)(local_mbar_addr)) : "memory")

#define CLUSTER_SYNC() do { \
    asm volatile("barrier.cluster.arrive.aligned;" ::: "memory"); \
    asm volatile("barrier.cluster.wait.aligned;" ::: "memory"); \
} while (0)

#define NAMED_BAR(id, cnt) \
    asm volatile("bar.sync %0, %1;" :: "r"(id), "r"(cnt) : "memory")

// bulk async copy global -> own-CTA shared, completion on LOCAL mbarrier
#define CP_BULK_G2S(dst_smem, src_gmem, bytes, mbar) \
    asm volatile("cp.async.bulk.shared::cluster.global.mbarrier::complete_tx::bytes " \
                 "[%0], [%1], %2, [%3];" \
        :: "r"((uint32_t)(dst_smem)), "l"(src_gmem), "r"((uint32_t)(bytes)), \
           "r"((uint32_t)(mbar)) : "memory")

// pack two floats to e4m3x2
__device__ __forceinline__ uint16_t f2e4m3x2(float lo, float hi) {
    uint16_t r;
    asm("cvt.rn.satfinite.e4m3x2.f32 %0, %1, %2;" : "=h"(r) : "f"(hi), "f"(lo));
    return r;
}

#if TC_OK
#define TCGEN05_ALLOC_CG2(smem_result_addr, nCols) \
    asm volatile("tcgen05.alloc.cta_group::2.sync.aligned.shared::cta.b32 [%0], %1;" \
        :: "r"((uint32_t)(smem_result_addr)), "r"((uint32_t)(nCols)) : "memory")

#define TCGEN05_DEALLOC_CG2(tmem_addr, nCols) \
    asm volatile("tcgen05.dealloc.cta_group::2.sync.aligned.b32 %0, %1;" \
        :: "r"(tmem_addr), "r"((uint32_t)(nCols)))

#define TCGEN05_RELINQUISH_CG2() \
    asm volatile("tcgen05.relinquish_alloc_permit.cta_group::2.sync.aligned;")

#define TCGEN05_COMMIT_MC_CG2(mbar_smem_addr, cta_mask) \
    asm volatile("tcgen05.commit.cta_group::2.mbarrier::arrive::one.shared::cluster.multicast::cluster.b64 [%0], %1;" \
        :: "r"((uint32_t)(mbar_smem_addr)), "h"((uint16_t)(cta_mask)) : "memory")

#define TCGEN05_WAIT_LD()  asm volatile("tcgen05.wait::ld.sync.aligned;" ::: "memory")
#define TCGEN05_WAIT_ST()  asm volatile("tcgen05.wait::st.sync.aligned;" ::: "memory")
#define TCGEN05_FENCE_BEFORE() asm volatile("tcgen05.fence::before_thread_sync;" ::: "memory")
#define TCGEN05_FENCE_AFTER()  asm volatile("tcgen05.fence::after_thread_sync;" ::: "memory")

#define TCGEN05_ST_32X32B_X1(tmem_addr, r0) \
    asm volatile("tcgen05.st.sync.aligned.32x32b.x1.b32 [%0], {%1};" \
        :: "r"(tmem_addr), "r"(r0) : "memory")

#define TCGEN05_LD_32X32B_X32(r, tmem_addr) \
    asm volatile( \
        "tcgen05.ld.sync.aligned.32x32b.x32.b32 " \
        "{%0, %1, %2, %3, %4, %5, %6, %7, " \
        " %8, %9, %10, %11, %12, %13, %14, %15, " \
        " %16, %17, %18, %19, %20, %21, %22, %23, " \
        " %24, %25, %26, %27, %28, %29, %30, %31}, [%32];" \
        : "=r"((r)[0]),  "=r"((r)[1]),  "=r"((r)[2]),  "=r"((r)[3]), \
          "=r"((r)[4]),  "=r"((r)[5]),  "=r"((r)[6]),  "=r"((r)[7]), \
          "=r"((r)[8]),  "=r"((r)[9]),  "=r"((r)[10]), "=r"((r)[11]), \
          "=r"((r)[12]), "=r"((r)[13]), "=r"((r)[14]), "=r"((r)[15]), \
          "=r"((r)[16]), "=r"((r)[17]), "=r"((r)[18]), "=r"((r)[19]), \
          "=r"((r)[20]), "=r"((r)[21]), "=r"((r)[22]), "=r"((r)[23]), \
          "=r"((r)[24]), "=r"((r)[25]), "=r"((r)[26]), "=r"((r)[27]), \
          "=r"((r)[28]), "=r"((r)[29]), "=r"((r)[30]), "=r"((r)[31]) \
        : "r"(tmem_addr))

// SW128 K-major SMEM descriptor (layout=SW128, Blackwell version=1, LBO=1, SBO=64)
static constexpr uint64_t SMEM_DESC_BASE_SW128 =
    (uint64_t(2) << 61) | (uint64_t(1) << 46) | (uint64_t(64) << 32) | (uint64_t(1) << 16);
#define MAKE_SMEM_DESC(base_addr) \
    (SMEM_DESC_BASE_SW128 | ((uint64_t)((base_addr) >> 4) & 0x3FFF))

// idesc for cta_group::2 kind::mxf8f6f4: M=256 (2<<27), UE8M0 (1<<23), N=128.
static constexpr uint32_t MXF8_IDESC_BASE =
    (2u << 27) | (1u << 23) | ((128u / 8) << 17);
__device__ __forceinline__ uint32_t mxf8_idesc(int k) {
    return MXF8_IDESC_BASE | ((uint32_t)k << 29) | ((uint32_t)k << 4);
}

// cg2 block-scaled MXFP8 SS MMA
__device__ __forceinline__ void mma_mxf8_ss_cg2(uint32_t d, uint64_t ad, uint64_t bd,
                                                uint32_t idesc, uint32_t sca,
                                                uint32_t scb, uint32_t acc) {
    asm volatile(
        "{\n\t.reg .pred p;\n\tsetp.ne.u32 p, %6, 0;\n\t"
        "tcgen05.mma.cta_group::2.kind::mxf8f6f4.block_scale.scale_vec::1X "
        "[%0], %1, %2, %3, [%4], [%5], p;\n\t}"
        :: "r"(d), "l"(ad), "l"(bd), "r"(idesc), "r"(sca), "r"(scb), "r"(acc)
        : "memory");
}
#endif  // TC_OK

// ---------------------------------------------------------------------------
// Persistent cg2 FP8 GEMM, A-resident + D ping-pong.
// Tile = 256 rows x 128 cols, K-chunk = 128; 16 tiles x 8 chunks per item.
// A (128KB) loaded once per item; B streamed through 8 x 8KB ring.
// TMEM: D0 @0[128), D1 @128[128), unit scales @256+.
// 192 threads: w0-3 epilogue, w4 producer lane, w5 MMA-issue lane (rank0).
//
// DEADLOCK FIX vs R13: at item boundaries the pending lag-1 relay of the
// previous item's last B chunk is flushed BEFORE waiting AEMPTY (AEMPTY
// depends on that chunk's MMAs -> its relay must precede the wait).
// In-loop relays run only for j >= 1.
// ---------------------------------------------------------------------------
static constexpr int TILE_N   = 128;
static constexpr int STAGES   = 8;

static constexpr uint32_t S_TMEM   = 0;
static constexpr uint32_t S_AFULLL = 16;                 // per CTA, tx 128KB
static constexpr uint32_t S_AFULLC = 24;                 // rank0, cnt=2
static constexpr uint32_t S_AEMPTY = 32;                 // per CTA (commit-mc)
static constexpr uint32_t S_FULLL  = 40;                 // 8 x 8B per CTA (tx 8KB)
static constexpr uint32_t S_FULLC  = 104;                // 8 x 8B rank0 (cnt=2)
static constexpr uint32_t S_EMPTY  = 168;                // 8 x 8B per CTA (cnt=1)
static constexpr uint32_t S_DONE0  = 232;                // per CTA (commit-mc)
static constexpr uint32_t S_DONE1  = 240;
static constexpr uint32_t S_EDONE0 = 248;                // rank0, cnt=2
static constexpr uint32_t S_EDONE1 = 256;
static constexpr uint32_t S_B1     = 1024;
static constexpr uint32_t S_W2     = 1024 + 4 * HID;         // 9216
static constexpr uint32_t S_A      = S_W2 + 4 * HID;         // 17408 (1024-aligned)
static constexpr uint32_t A_BYTES  = 131072;                 // 128 rows x 1024 k fp8
static constexpr uint32_t S_B      = S_A + A_BYTES;          // 148480
static constexpr uint32_t B_STAGE_BYTES = 8192;              // 64 n-rows x 128 B
static constexpr uint32_t SMEM_BYTES = S_B + STAGES * B_STAGE_BYTES; // 214016

__global__ void __launch_bounds__(192, 1) __cluster_dims__(2, 1, 1)
gemm_fused(const float* __restrict__ b1, const float* __restrict__ W2) {
#if TC_OK
    extern __shared__ __align__(1024) uint8_t smem[];
    const uint32_t sb = smem_to_u32(smem);
    const int tid  = threadIdx.x;
    const int wid  = tid >> 5;
    const uint32_t rank = cluster_rank();
    const int cid  = blockIdx.x >> 1;              // cluster id 0..73

    const int nwork = (N_WORK - cid + N_CLUSTERS - 1) / N_CLUSTERS;  // 13 or 12
    const int KKT   = nwork * 128;                 // total B chunks, flat
    const int NTT   = nwork * 16;                  // total 128-col tiles, flat

    if (wid == 0) TCGEN05_ALLOC_CG2(sb + S_TMEM, 512);
    if (tid == 0) {
        if (rank == 0) {
            MBARRIER_INIT(sb + S_AFULLC, 2);
            for (int s = 0; s < STAGES; s++) MBARRIER_INIT(sb + S_FULLC + 8 * s, 2);
            MBARRIER_INIT(sb + S_EDONE0, 2);
            MBARRIER_INIT(sb + S_EDONE1, 2);
        }
        MBARRIER_INIT(sb + S_AFULLL, 1);
        MBARRIER_INIT(sb + S_AEMPTY, 1);
        for (int s = 0; s < STAGES; s++) {
            MBARRIER_INIT(sb + S_FULLL + 8 * s, 1);   // expect_tx arms each phase
            MBARRIER_INIT(sb + S_EMPTY + 8 * s, 1);
        }
        MBARRIER_INIT(sb + S_DONE0, 1);
        MBARRIER_INIT(sb + S_DONE1, 1);
    }
    __syncthreads();

    uint32_t tmem;
    asm volatile("ld.shared.b32 %0, [%1];" : "=r"(tmem) : "r"(sb + S_TMEM));

    float* s_b1 = (float*)(smem + S_B1);
    float* s_w2 = (float*)(smem + S_W2);
    if (tid < 128) {
        const int e0 = cid >> 5;
        for (int i = tid; i < HID; i += 128) {
            s_b1[i] = __ldg(b1 + (size_t)e0 * HID + i);
            s_w2[i] = __ldg(W2 + (size_t)e0 * HID + i);
        }
        // unit ue8m0 scales (127 = 2^0), SCA @256..259 + SCB @260..263, replicated
        const uint32_t wo = (uint32_t)(tid >> 5) << 21;
#pragma unroll
        for (int c = 0; c < 8; c++)
            TCGEN05_ST_32X32B_X1(tmem + 256 + c + wo, 0x7F7F7F7Fu);
        TCGEN05_WAIT_ST();
        TCGEN05_FENCE_BEFORE();
    }
    __syncthreads();
    CLUSTER_SYNC();   // barriers + scales ready cluster-wide before any arrival/tx

    if (wid == 4) {
        // =================== PRODUCER LANE (both CTAs) ===================
        if (elect_one_pred()) {
            const char* xa = (const char*)g_xa;
            const char* wb = (const char*)g_wb;

            for (int w = 0; w < nwork; w++) {
                const int wk = cid + N_CLUSTERS * w;
                const int e_w = wk >> 5;
                const int mb  = (wk & 31) * 2 + (int)rank;   // m-block of 128

                // ---- item boundary: FLUSH pending relay, THEN wait AEMPTY ----
                if (w >= 1) {
                    const int p = w * 128 - 1;    // last chunk of previous item
                    MBARRIER_WAIT_PARITY(sb + S_FULLL + 8 * (p & 7), (p >> 3) & 1);
                    MBARRIER_ARRIVE_RANK0(sb + S_FULLC + 8 * (p & 7));
                    MBARRIER_WAIT_PARITY(sb + S_AEMPTY, (w - 1) & 1);
                }

                // ---- A: 128KB resident, 8 bulks, 1 tx barrier ----
                MBARRIER_EXPECT_TX(sb + S_AFULLL, A_BYTES);
                const char* asrc = xa + ((size_t)mb << 17);
#pragma unroll
                for (int kc = 0; kc < 8; kc++)
                    CP_BULK_G2S(sb + S_A + (uint32_t)kc * 16384u,
                                asrc + ((size_t)kc << 14), 16384, sb + S_AFULLL);

                // ---- B: 128 chunks of 8KB through the ring ----
                for (int j = 0; j < 128; j++) {
                    const int la = w * 128 + j;
                    const int s  = la & 7;
                    const int u  = la >> 3;
                    if (u >= 1)
                        MBARRIER_WAIT_PARITY(sb + S_EMPTY + 8 * s, (u - 1) & 1);

                    const int tile = j >> 3;
                    const int kc   = j & 7;
                    MBARRIER_EXPECT_TX(sb + S_FULLL + 8 * s, B_STAGE_BYTES);
                    const size_t boff =
                        ((size_t)(((e_w * 16 + tile) * 2 + (int)rank) * 8 + kc)) << 13;
                    CP_BULK_G2S(sb + S_B + (uint32_t)s * B_STAGE_BYTES,
                                wb + boff, B_STAGE_BYTES, sb + S_FULLL + 8 * s);

                    // relay previous B chunk (within-item only; j==0 handled above)
                    if (j >= 1) {
                        const int p = la - 1;
                        MBARRIER_WAIT_PARITY(sb + S_FULLL + 8 * (p & 7), (p >> 3) & 1);
                        MBARRIER_ARRIVE_RANK0(sb + S_FULLC + 8 * (p & 7));
                    }
                    // relay A completion once, early in the item
                    if (j == 1) {
                        MBARRIER_WAIT_PARITY(sb + S_AFULLL, w & 1);
                        MBARRIER_ARRIVE_RANK0(sb + S_AFULLC);
                    }
                }
            }
            // relay final B chunk
            const int p = KKT - 1;
            MBARRIER_WAIT_PARITY(sb + S_FULLL + 8 * (p & 7), (p >> 3) & 1);
            MBARRIER_ARRIVE_RANK0(sb + S_FULLC + 8 * (p & 7));
        }
    } else if (wid == 5) {
        // =================== MMA ISSUE LANE (rank 0 only) ===================
        if (rank == 0 && elect_one_pred()) {
            for (int w = 0; w < nwork; w++) {
                MBARRIER_WAIT_PARITY_CLU(sb + S_AFULLC, w & 1);   // A ready, both CTAs
                for (int tile = 0; tile < 16; tile++) {
                    const int tt  = w * 16 + tile;
                    const int buf = tt & 1;
                    const uint32_t dbase = tmem + (uint32_t)buf * 128;
                    if (tt >= 2)
                        MBARRIER_WAIT_PARITY_CLU(sb + (buf ? S_EDONE1 : S_EDONE0),
                                                 ((tt >> 1) - 1) & 1);
                    for (int kc = 0; kc < 8; kc++) {
                        const int kb = tt * 8 + kc;
                        const int s  = kb & 7;
                        MBARRIER_WAIT_PARITY_CLU(sb + S_FULLC + 8 * s, (kb >> 3) & 1);
                        TCGEN05_FENCE_AFTER();
                        const uint64_t ad = MAKE_SMEM_DESC(sb + S_A + (uint32_t)kc * 16384u);
                        const uint64_t bd = MAKE_SMEM_DESC(sb + S_B + (uint32_t)s * B_STAGE_BYTES);
#pragma unroll
                        for (int ks = 0; ks < 4; ks++)     // 4 x K32 per 128-chunk
                            mma_mxf8_ss_cg2(dbase, ad + ks * 2, bd + ks * 2,
                                            mxf8_idesc(ks),
                                            tmem + 256, tmem + 260,
                                            (uint32_t)((kc | ks) != 0));
                        TCGEN05_COMMIT_MC_CG2(sb + S_EMPTY + 8 * s, 0x3);
                    }
                    TCGEN05_COMMIT_MC_CG2(sb + (buf ? S_DONE1 : S_DONE0), 0x3);
                }
                TCGEN05_COMMIT_MC_CG2(sb + S_AEMPTY, 0x3);   // all item MMAs done
            }
        }
    } else {
        // =================== EPILOGUE WARPS (0-3) ===================
        float zacc[4] = {0.f, 0.f, 0.f, 0.f};

        for (int tt = 0; tt < NTT; tt++) {
            const int buf = tt & 1;
            const uint32_t dbase = tmem + (uint32_t)buf * 128;
            MBARRIER_WAIT_PARITY(sb + (buf ? S_DONE1 : S_DONE0), (tt >> 1) & 1);
            TCGEN05_FENCE_AFTER();

            uint32_t bufA[32], bufB[32];
            TCGEN05_LD_32X32B_X32(bufA, dbase);
            TCGEN05_WAIT_LD();
#pragma unroll
            for (int ch = 0; ch < 4; ch++) {
                if (ch < 3) {          // prefetch next chunk while consuming current
                    if (ch & 1) { TCGEN05_LD_32X32B_X32(bufA, dbase + (ch + 1) * 32); }
                    else        { TCGEN05_LD_32X32B_X32(bufB, dbase + (ch + 1) * 32); }
                }
                const uint32_t* cur = (ch & 1) ? bufB : bufA;
                const int nb = (tt & 15) * TILE_N + ch * 32;
#pragma unroll
                for (int c = 0; c < 32; c++) {
                    float h = fmaf(__uint_as_float(cur[c]), INV_SCALE, s_b1[nb + c]);
                    h = fmaxf(h, 0.f);
                    zacc[c & 3] = fmaf(h, s_w2[nb + c], zacc[c & 3]);
                }
                if (ch < 3) TCGEN05_WAIT_LD();
            }
            TCGEN05_FENCE_BEFORE();
            NAMED_BAR(2, 128);          // all 4 epilogue warps done reading this buf
            if (tid == 0) MBARRIER_ARRIVE_RANK0(sb + (buf ? S_EDONE1 : S_EDONE0));

            if ((tt & 15) == 15) {
                // ---- end of work item: emit z, reset, load next b1/W2 ----
                const int w  = tt >> 4;
                const int wk = cid + N_CLUSTERS * w;
                const int e_w = wk >> 5;
                const int m0w = (wk & 31) * 256 + (int)rank * 128;
                const float z = (zacc[0] + zacc[1]) + (zacc[2] + zacc[3]);
                g_zbuf[(size_t)e_w * BATCH_SZ + m0w + tid] = z;
                zacc[0] = zacc[1] = zacc[2] = zacc[3] = 0.f;

                if (w + 1 < nwork) {
                    const int e_n = (cid + N_CLUSTERS * (w + 1)) >> 5;
                    for (int i = tid; i < HID; i += 128) {
                        s_b1[i] = __ldg(b1 + (size_t)e_n * HID + i);
                        s_w2[i] = __ldg(W2 + (size_t)e_n * HID + i);
                    }
                }
                NAMED_BAR(2, 128);      // reload visible before next epilogue
            }
        }
    }

    __syncthreads();
    if (wid == 0) {
        TCGEN05_RELINQUISH_CG2();
        TCGEN05_DEALLOC_CG2(tmem, 512);
    }
    CLUSTER_SYNC();   // peer MMAs/multicasts targeting our SMEM must be done
#endif  // TC_OK
}

// ---------------------------------------------------------------------------
// Host/device shared swizzle
// ---------------------------------------------------------------------------
__device__ __forceinline__ uint32_t swz128(uint32_t o) {
    return o ^ ((o >> 3) & 0x70);
}

// x fp32 [B][K] -> g_xa fp8 blobs (scaled by 2^6); 16 k per thread.
__global__ void cvt_x_kernel(const float* __restrict__ x) {
    const int i = blockIdx.x * blockDim.x + threadIdx.x;   // < 8192*64
    const int m = i >> 6;
    const int g = i & 63;               // 16B group; kc = g>>3
    const float* src = x + (size_t)m * IN_SZ + g * 16;
    float v[16];
#pragma unroll
    for (int j = 0; j < 16; j++) v[j] = src[j] * X_SCALE;
    uint32_t w[4];
#pragma unroll
    for (int q = 0; q < 4; q++) {
        const uint16_t p01 = f2e4m3x2(v[4 * q + 0], v[4 * q + 1]);
        const uint16_t p23 = f2e4m3x2(v[4 * q + 2], v[4 * q + 3]);
        w[q] = (uint32_t)p01 | ((uint32_t)p23 << 16);
    }
    uint4 out = make_uint4(w[0], w[1], w[2], w[3]);
    const int mb = m >> 7, r = m & 127, kc = g >> 3;
    const uint32_t off = swz128((uint32_t)(r * 128 + (g & 7) * 16));
    *(uint4*)((char*)g_xa + (((size_t)(mb * 8 + kc)) << 14) + off) = out;
}

// W1 fp32 [E][K][H] -> g_wb fp8 8KB blobs (scaled by 2^13), K-major.
// blob(e, tile16, rank, kc8): row = hid&63, rank=(hid>>6)&1, tile=hid>>7.
__global__ void cvt_w1_kernel(const float* __restrict__ W1) {
    __shared__ float tile[128][33];
    const int e  = blockIdx.z;
    const int kc = blockIdx.y;          // K-chunk of 128
    const int hb = blockIdx.x;          // hid block of 32
    const int t  = threadIdx.x;         // 0..255
    const float* src = W1 + ((size_t)e * IN_SZ + kc * 128) * HID + hb * 32;
#pragma unroll
    for (int it = 0; it < 16; it++) {
        const int lin = it * 256 + t;   // < 4096 = 128k x 32h
        const int kr = lin >> 5, hc = lin & 31;
        tile[kr][hc] = src[(size_t)kr * HID + hc];
    }
    __syncthreads();
    const int h = t >> 3, g = t & 7;    // h: 0..31, g: 16B group 0..7
    float v[16];
#pragma unroll
    for (int j = 0; j < 16; j++) v[j] = tile[g * 16 + j][h] * W_SCALE;
    uint32_t w[4];
#pragma unroll
    for (int q = 0; q < 4; q++) {
        const uint16_t p01 = f2e4m3x2(v[4 * q + 0], v[4 * q + 1]);
        const uint16_t p23 = f2e4m3x2(v[4 * q + 2], v[4 * q + 3]);
        w[q] = (uint32_t)p01 | ((uint32_t)p23 << 16);
    }
    uint4 out = make_uint4(w[0], w[1], w[2], w[3]);
    const int hid = hb * 32 + h;
    const int tl  = hid >> 7;           // 128-col N tile
    const int rk  = (hid >> 6) & 1;
    const int row = hid & 63;
    const size_t blob = (size_t)(((e * 16 + tl) * 2 + rk) * 8 + kc);
    const uint32_t off = swz128((uint32_t)(row * 128 + g * 16));
    *(uint4*)((char*)g_wb + (blob << 13) + off) = out;
}

// ---------------------------------------------------------------------------
// Final reduce: out[m] = mean_e sigmoid(z[e][m] + b2[e]); 4 threads/output
// ---------------------------------------------------------------------------
__global__ void reduce_kernel(const float* __restrict__ b2, float* __restrict__ out) {
    const int tid = blockIdx.x * blockDim.x + threadIdx.x;  // < 32768
    const int i = tid >> 2, l = tid & 3;
    float s = 0.f;
#pragma unroll
    for (int ex = l; ex < N_EXPERTS; ex += 4) {
        const float z = g_zbuf[(size_t)ex * BATCH_SZ + i] + b2[ex];
        s += 1.f / (1.f + __expf(-z));
    }
    s += __shfl_xor_sync(0xFFFFFFFFu, s, 1);
    s += __shfl_xor_sync(0xFFFFFFFFu, s, 2);
    if (l == 0) out[i] = s * (1.f / N_EXPERTS);
}

// ---------------------------------------------------------------------------
// Harness entry
// ---------------------------------------------------------------------------
extern "C" void kernel_launch(void* const* d_in, const int* in_sizes, int n_in,
                              void* d_out, int out_size) {
    (void)in_sizes; (void)n_in; (void)out_size;
    const float* x  = (const float*)d_in[0];
    const float* W1 = (const float*)d_in[1];
    const float* b1 = (const float*)d_in[2];
    const float* W2 = (const float*)d_in[3];
    const float* b2 = (const float*)d_in[4];
    float* out = (float*)d_out;

    cudaFuncSetAttribute(gemm_fused, cudaFuncAttributeMaxDynamicSharedMemorySize,
                         (int)SMEM_BYTES);

    cvt_x_kernel<<<(BATCH_SZ * 64) / 256, 256>>>(x);

    dim3 tg(HID / 32, IN_SZ / 128, N_EXPERTS);   // (hb, kc, e)
    cvt_w1_kernel<<<tg, 256>>>(W1);

    // persistent: 148 CTAs = 74 cg2 clusters
    gemm_fused<<<2 * N_CLUSTERS, 192, SMEM_BYTES>>>(b1, W2);

    reduce_kernel<<<(BATCH_SZ * 4) / 256, 256>>>(b2, out);
}

// round 15
// speedup vs baseline: 1.2894x; 1.2894x over previous
#include <cuda_runtime.h>
#include <cuda_bf16.h>
#include <cstdint>

// ---------------------------------------------------------------------------
// Arch gate: tcgen05 is sm_103a-ONLY (plain compute_103 phase must compile).
// ---------------------------------------------------------------------------
#if defined(__CUDA_ARCH__) && (__CUDA_ARCH__ == 1030) && defined(__CUDA_ARCH_FEAT_SM103_ALL)
#define TC_OK 1
#else
#define TC_OK 0
#endif

// ---------------------------------------------------------------------------
// Problem constants
// ---------------------------------------------------------------------------
#define N_EXPERTS 30
#define IN_SZ     1024
#define HID       2048
#define BATCH_SZ  8192

#define N_CLUSTERS 74            // 148 CTAs / 2
#define N_WORK     960           // 30 experts * 32 m-blocks of 256

// Exact power-of-2 operand scaling (folded out in epilogue)
#define X_SCALE   64.0f          // 2^6:  |x|max ~5.4 -> ~350 < 448
#define W_SCALE   8192.0f        // 2^13: |w|max 1/32 -> 256 < 448
#define INV_SCALE 1.9073486328125e-6f   // 2^-19 exact

// ---------------------------------------------------------------------------
// Device scratch (fp8 e4m3 blobs, SW128-swizzled SMEM images).
// g_xa: A blob(mb128, kc8) = 16KB: x rows [mb*128,+128), k [kc*128,+128).
//       kc-contiguous -> one m-block's full A = 128KB contiguous.
// g_wb: B blob(e, nt8, rank, kc8) = 16KB: 128 n-rows x 128B where
//       hid = nt*256 + rank*128 + row, k [kc*128,+128).
// ---------------------------------------------------------------------------
__device__ __align__(16) uint8_t g_xa[(size_t)BATCH_SZ * IN_SZ];                 // 8 MB
__device__ __align__(16) uint8_t g_wb[(size_t)N_EXPERTS * HID * IN_SZ];          // 63 MB
__device__ float g_zbuf[(size_t)N_EXPERTS * BATCH_SZ];                            // 1 MB

// ---------------------------------------------------------------------------
// PTX helpers
// ---------------------------------------------------------------------------
__device__ __forceinline__ uint32_t smem_to_u32(const void* p) {
    uint32_t a;
    asm("{ .reg .u64 t; cvta.to.shared.u64 t, %1; cvt.u32.u64 %0, t; }"
        : "=r"(a) : "l"(p));
    return a;
}

__device__ __forceinline__ uint32_t elect_one_pred() {
    uint32_t pred;
    asm volatile(
        "{\n\t.reg .pred p;\n\telect.sync _|p, 0xFFFFFFFF;\n\tselp.b32 %0, 1, 0, p;\n\t}"
        : "=r"(pred));
    return pred;
}

__device__ __forceinline__ uint32_t cluster_rank() {
    uint32_t r;
    asm("mov.u32 %0, %%cluster_ctarank;" : "=r"(r));
    return r;
}

#define MBARRIER_INIT(addr, cnt) \
    asm volatile("mbarrier.init.shared.b64 [%0], %1;" :: "r"((uint32_t)(addr)), "r"((uint32_t)(cnt)) : "memory")

#define MBARRIER_EXPECT_TX(addr, bytes) \
    asm volatile("mbarrier.arrive.expect_tx.shared.b64 _, [%0], %1;" \
        :: "r"((uint32_t)(addr)), "r"((uint32_t)(bytes)) : "memory")

// local wait, acquire at cta scope
#define MBARRIER_WAIT_PARITY(mbar_smem_addr, phase_parity) do { \
    uint32_t _mbar = (uint32_t)(mbar_smem_addr); \
    uint32_t _parity = (uint32_t)(phase_parity); \
    uint32_t _done; \
    asm volatile( \
        "{\n\t.reg .pred p;\n\t" \
        "mbarrier.try_wait.parity.acquire.cta.shared::cta.b64 p, [%1], %2;\n\t" \
        "selp.b32 %0, 1, 0, p;\n\t}" \
        : "=r"(_done) : "r"(_mbar), "r"(_parity) : "memory"); \
    if (!_done) { \
        asm volatile( \
            "{\n\t.reg .pred P1;\n\t" \
            "WAIT_LOOP_%=:\n\t" \
            "mbarrier.try_wait.parity.acquire.cta.shared::cta.b64 P1, [%0], %1, 0x989680;\n\t" \
            "@P1 bra.uni WAIT_DONE_%=;\n\t" \
            "bra.uni WAIT_LOOP_%=;\n\t" \
            "WAIT_DONE_%=:\n\t}" \
            :: "r"(_mbar), "r"(_parity) : "memory"); \
    } \
} while (0)

// cluster-scope acquire wait (peer-signaled barriers / peer data)
#define MBARRIER_WAIT_PARITY_CLU(mbar_smem_addr, phase_parity) do { \
    uint32_t _mbar = (uint32_t)(mbar_smem_addr); \
    uint32_t _parity = (uint32_t)(phase_parity); \
    uint32_t _done; \
    asm volatile( \
        "{\n\t.reg .pred p;\n\t" \
        "mbarrier.try_wait.parity.acquire.cluster.shared::cta.b64 p, [%1], %2;\n\t" \
        "selp.b32 %0, 1, 0, p;\n\t}" \
        : "=r"(_done) : "r"(_mbar), "r"(_parity) : "memory"); \
    if (!_done) { \
        asm volatile( \
            "{\n\t.reg .pred P1;\n\t" \
            "WAIT_LOOP_%=:\n\t" \
            "mbarrier.try_wait.parity.acquire.cluster.shared::cta.b64 P1, [%0], %1, 0x989680;\n\t" \
            "@P1 bra.uni WAIT_DONE_%=;\n\t" \
            "bra.uni WAIT_LOOP_%=;\n\t" \
            "WAIT_DONE_%=:\n\t}" \
            :: "r"(_mbar), "r"(_parity) : "memory"); \
    } \
} while (0)

// arrive on the same-offset mbarrier in cluster rank 0
#define MBARRIER_ARRIVE_RANK0(local_mbar_addr) \
    asm volatile( \
        "{\n\t.reg .b32 remAddr32;\n\t" \
        "mapa.shared::cluster.u32 remAddr32, %0, 0;\n\t" \
        "mbarrier.arrive.shared::cluster.b64 _, [remAddr32];\n\t}" \
        :: "r"((uint32_t)(local_mbar_addr)) : "memory")

#define CLUSTER_SYNC() do { \
    asm volatile("barrier.cluster.arrive.aligned;" ::: "memory"); \
    asm volatile("barrier.cluster.wait.aligned;" ::: "memory"); \
} while (0)

#define NAMED_BAR(id, cnt) \
    asm volatile("bar.sync %0, %1;" :: "r"(id), "r"(cnt) : "memory")

// bulk async copy global -> own-CTA shared, completion on LOCAL mbarrier
#define CP_BULK_G2S(dst_smem, src_gmem, bytes, mbar) \
    asm volatile("cp.async.bulk.shared::cluster.global.mbarrier::complete_tx::bytes " \
                 "[%0], [%1], %2, [%3];" \
        :: "r"((uint32_t)(dst_smem)), "l"(src_gmem), "r"((uint32_t)(bytes)), \
           "r"((uint32_t)(mbar)) : "memory")

// pack two floats to e4m3x2
__device__ __forceinline__ uint16_t f2e4m3x2(float lo, float hi) {
    uint16_t r;
    asm("cvt.rn.satfinite.e4m3x2.f32 %0, %1, %2;" : "=h"(r) : "f"(hi), "f"(lo));
    return r;
}

#if TC_OK
#define TCGEN05_ALLOC_CG2(smem_result_addr, nCols) \
    asm volatile("tcgen05.alloc.cta_group::2.sync.aligned.shared::cta.b32 [%0], %1;" \
        :: "r"((uint32_t)(smem_result_addr)), "r"((uint32_t)(nCols)) : "memory")

#define TCGEN05_DEALLOC_CG2(tmem_addr, nCols) \
    asm volatile("tcgen05.dealloc.cta_group::2.sync.aligned.b32 %0, %1;" \
        :: "r"(tmem_addr), "r"((uint32_t)(nCols)))

#define TCGEN05_RELINQUISH_CG2() \
    asm volatile("tcgen05.relinquish_alloc_permit.cta_group::2.sync.aligned;")

#define TCGEN05_COMMIT_MC_CG2(mbar_smem_addr, cta_mask) \
    asm volatile("tcgen05.commit.cta_group::2.mbarrier::arrive::one.shared::cluster.multicast::cluster.b64 [%0], %1;" \
        :: "r"((uint32_t)(mbar_smem_addr)), "h"((uint16_t)(cta_mask)) : "memory")

#define TCGEN05_WAIT_LD()  asm volatile("tcgen05.wait::ld.sync.aligned;" ::: "memory")
#define TCGEN05_WAIT_ST()  asm volatile("tcgen05.wait::st.sync.aligned;" ::: "memory")
#define TCGEN05_FENCE_BEFORE() asm volatile("tcgen05.fence::before_thread_sync;" ::: "memory")
#define TCGEN05_FENCE_AFTER()  asm volatile("tcgen05.fence::after_thread_sync;" ::: "memory")

#define TCGEN05_ST_32X32B_X1(tmem_addr, r0) \
    asm volatile("tcgen05.st.sync.aligned.32x32b.x1.b32 [%0], {%1};" \
        :: "r"(tmem_addr), "r"(r0) : "memory")

#define TCGEN05_LD_32X32B_X32(r, tmem_addr) \
    asm volatile( \
        "tcgen05.ld.sync.aligned.32x32b.x32.b32 " \
        "{%0, %1, %2, %3, %4, %5, %6, %7, " \
        " %8, %9, %10, %11, %12, %13, %14, %15, " \
        " %16, %17, %18, %19, %20, %21, %22, %23, " \
        " %24, %25, %26, %27, %28, %29, %30, %31}, [%32];" \
        : "=r"((r)[0]),  "=r"((r)[1]),  "=r"((r)[2]),  "=r"((r)[3]), \
          "=r"((r)[4]),  "=r"((r)[5]),  "=r"((r)[6]),  "=r"((r)[7]), \
          "=r"((r)[8]),  "=r"((r)[9]),  "=r"((r)[10]), "=r"((r)[11]), \
          "=r"((r)[12]), "=r"((r)[13]), "=r"((r)[14]), "=r"((r)[15]), \
          "=r"((r)[16]), "=r"((r)[17]), "=r"((r)[18]), "=r"((r)[19]), \
          "=r"((r)[20]), "=r"((r)[21]), "=r"((r)[22]), "=r"((r)[23]), \
          "=r"((r)[24]), "=r"((r)[25]), "=r"((r)[26]), "=r"((r)[27]), \
          "=r"((r)[28]), "=r"((r)[29]), "=r"((r)[30]), "=r"((r)[31]) \
        : "r"(tmem_addr))

// SW128 K-major SMEM descriptor (layout=SW128, Blackwell version=1, LBO=1, SBO=64)
static constexpr uint64_t SMEM_DESC_BASE_SW128 =
    (uint64_t(2) << 61) | (uint64_t(1) << 46) | (uint64_t(64) << 32) | (uint64_t(1) << 16);
#define MAKE_SMEM_DESC(base_addr) \
    (SMEM_DESC_BASE_SW128 | ((uint64_t)((base_addr) >> 4) & 0x3FFF))

// idesc for cta_group::2 kind::mxf8f6f4: M=256 (2<<27), UE8M0 (1<<23), N=256.
static constexpr uint32_t MXF8_IDESC_BASE =
    (2u << 27) | (1u << 23) | ((256u / 8) << 17);
__device__ __forceinline__ uint32_t mxf8_idesc(int k) {
    return MXF8_IDESC_BASE | ((uint32_t)k << 29) | ((uint32_t)k << 4);
}

// cg2 block-scaled MXFP8 SS MMA
__device__ __forceinline__ void mma_mxf8_ss_cg2(uint32_t d, uint64_t ad, uint64_t bd,
                                                uint32_t idesc, uint32_t sca,
                                                uint32_t scb, uint32_t acc) {
    asm volatile(
        "{\n\t.reg .pred p;\n\tsetp.ne.u32 p, %6, 0;\n\t"
        "tcgen05.mma.cta_group::2.kind::mxf8f6f4.block_scale.scale_vec::1X "
        "[%0], %1, %2, %3, [%4], [%5], p;\n\t}"
        :: "r"(d), "l"(ad), "l"(bd), "r"(idesc), "r"(sca), "r"(scb), "r"(acc)
        : "memory");
}
#endif  // TC_OK

// ---------------------------------------------------------------------------
// Persistent cg2 FP8 GEMM: R12's proven N=256-tile machinery + A-resident.
// Tile = 256 rows x 256 cols; K-chunk = 128; 8 tiles x 8 chunks = 64/item.
// A (128KB) bulk-loaded once per item into resident SMEM; B streamed
// through the R12 4 x 16KB ring. TMEM: D 256 cols @0; scales @256+.
// 192 threads: w0-3 epilogue, w4 producer lane, w5 MMA-issue lane (rank0).
// Item boundary ordering (R14-proven): flush pending B relay -> wait AEMPTY
// -> load A. In-loop relays only for j >= 1.
// ---------------------------------------------------------------------------
static constexpr int TILE_N   = 256;
static constexpr int STAGES   = 4;

static constexpr uint32_t S_TMEM   = 0;
static constexpr uint32_t S_AFULLL = 16;                 // per CTA, tx 128KB
static constexpr uint32_t S_AFULLC = 24;                 // rank0, cnt=2
static constexpr uint32_t S_AEMPTY = 32;                 // per CTA (commit-mc)
static constexpr uint32_t S_FULLL  = 40;                 // 4 x 8B per CTA (tx 16KB)
static constexpr uint32_t S_FULLC  = 72;                 // 4 x 8B rank0 (cnt=2)
static constexpr uint32_t S_EMPTY  = 104;                // 4 x 8B per CTA (cnt=1)
static constexpr uint32_t S_DONE   = 136;                // per CTA (commit-mc)
static constexpr uint32_t S_EDONE  = 144;                // rank0, cnt=2
static constexpr uint32_t S_B1     = 1024;
static constexpr uint32_t S_W2     = 1024 + 4 * HID;         // 9216
static constexpr uint32_t S_A      = S_W2 + 4 * HID;         // 17408 (1024-aligned)
static constexpr uint32_t A_BYTES  = 131072;                 // 128 rows x 1024 k fp8
static constexpr uint32_t S_B      = S_A + A_BYTES;          // 148480
static constexpr uint32_t B_STAGE_BYTES = 16384;             // 128 n-rows x 128 B
static constexpr uint32_t SMEM_BYTES = S_B + STAGES * B_STAGE_BYTES; // 214016

__global__ void __launch_bounds__(192, 1) __cluster_dims__(2, 1, 1)
gemm_fused(const float* __restrict__ b1, const float* __restrict__ W2) {
#if TC_OK
    extern __shared__ __align__(1024) uint8_t smem[];
    const uint32_t sb = smem_to_u32(smem);
    const int tid  = threadIdx.x;
    const int wid  = tid >> 5;
    const uint32_t rank = cluster_rank();
    const int cid  = blockIdx.x >> 1;              // cluster id 0..73

    const int nwork = (N_WORK - cid + N_CLUSTERS - 1) / N_CLUSTERS;  // 13 or 12
    const int KKT   = nwork * 64;                  // total B chunks, flat
    const int NTT   = nwork * 8;                   // total 256-col tiles, flat

    if (wid == 0) TCGEN05_ALLOC_CG2(sb + S_TMEM, 512);
    if (tid == 0) {
        if (rank == 0) {
            MBARRIER_INIT(sb + S_AFULLC, 2);
            for (int s = 0; s < STAGES; s++) MBARRIER_INIT(sb + S_FULLC + 8 * s, 2);
            MBARRIER_INIT(sb + S_EDONE, 2);
        }
        MBARRIER_INIT(sb + S_AFULLL, 1);
        MBARRIER_INIT(sb + S_AEMPTY, 1);
        for (int s = 0; s < STAGES; s++) {
            MBARRIER_INIT(sb + S_FULLL + 8 * s, 1);   // expect_tx arms each phase
            MBARRIER_INIT(sb + S_EMPTY + 8 * s, 1);
        }
        MBARRIER_INIT(sb + S_DONE, 1);
    }
    __syncthreads();

    uint32_t tmem;
    asm volatile("ld.shared.b32 %0, [%1];" : "=r"(tmem) : "r"(sb + S_TMEM));

    float* s_b1 = (float*)(smem + S_B1);
    float* s_w2 = (float*)(smem + S_W2);
    if (tid < 128) {
        const int e0 = cid >> 5;
        for (int i = tid; i < HID; i += 128) {
            s_b1[i] = __ldg(b1 + (size_t)e0 * HID + i);
            s_w2[i] = __ldg(W2 + (size_t)e0 * HID + i);
        }
        // unit ue8m0 scales (127 = 2^0): SCA @256..259 + SCB @260..267, replicated
        const uint32_t wo = (uint32_t)(tid >> 5) << 21;
#pragma unroll
        for (int c = 0; c < 12; c++)
            TCGEN05_ST_32X32B_X1(tmem + 256 + c + wo, 0x7F7F7F7Fu);
        TCGEN05_WAIT_ST();
        TCGEN05_FENCE_BEFORE();
    }
    __syncthreads();
    CLUSTER_SYNC();   // barriers + scales ready cluster-wide before any arrival/tx

    if (wid == 4) {
        // =================== PRODUCER LANE (both CTAs) ===================
        if (elect_one_pred()) {
            const char* xa = (const char*)g_xa;
            const char* wb = (const char*)g_wb;

            for (int w = 0; w < nwork; w++) {
                const int wk = cid + N_CLUSTERS * w;
                const int e_w = wk >> 5;
                const int mb  = (wk & 31) * 2 + (int)rank;   // m-block of 128

                // ---- item boundary: FLUSH pending relay, THEN wait AEMPTY ----
                if (w >= 1) {
                    const int p = w * 64 - 1;     // last chunk of previous item
                    MBARRIER_WAIT_PARITY(sb + S_FULLL + 8 * (p & 3), (p >> 2) & 1);
                    MBARRIER_ARRIVE_RANK0(sb + S_FULLC + 8 * (p & 3));
                    MBARRIER_WAIT_PARITY(sb + S_AEMPTY, (w - 1) & 1);
                }

                // ---- A: 128KB resident, 8 bulks, 1 tx barrier ----
                MBARRIER_EXPECT_TX(sb + S_AFULLL, A_BYTES);
                const char* asrc = xa + ((size_t)mb << 17);
#pragma unroll
                for (int kc = 0; kc < 8; kc++)
                    CP_BULK_G2S(sb + S_A + (uint32_t)kc * 16384u,
                                asrc + ((size_t)kc << 14), 16384, sb + S_AFULLL);

                // ---- B: 64 chunks of 16KB through the ring ----
                for (int j = 0; j < 64; j++) {
                    const int la = w * 64 + j;
                    const int s  = la & 3;
                    const int u  = la >> 2;
                    if (u >= 1)
                        MBARRIER_WAIT_PARITY(sb + S_EMPTY + 8 * s, (u - 1) & 1);

                    const int nt = j >> 3;        // N-tile of 256
                    const int kc = j & 7;         // K-chunk of 128
                    MBARRIER_EXPECT_TX(sb + S_FULLL + 8 * s, B_STAGE_BYTES);
                    const size_t boff =
                        ((size_t)(e_w * 128 + nt * 16 + (int)rank * 8 + kc)) << 14;
                    CP_BULK_G2S(sb + S_B + (uint32_t)s * B_STAGE_BYTES,
                                wb + boff, B_STAGE_BYTES, sb + S_FULLL + 8 * s);

                    // relay previous B chunk (within-item; j==0 handled at boundary)
                    if (j >= 1) {
                        const int p = la - 1;
                        MBARRIER_WAIT_PARITY(sb + S_FULLL + 8 * (p & 3), (p >> 2) & 1);
                        MBARRIER_ARRIVE_RANK0(sb + S_FULLC + 8 * (p & 3));
                    }
                    // relay A completion once, early in the item
                    if (j == 1) {
                        MBARRIER_WAIT_PARITY(sb + S_AFULLL, w & 1);
                        MBARRIER_ARRIVE_RANK0(sb + S_AFULLC);
                    }
                }
            }
            // relay final B chunk
            const int p = KKT - 1;
            MBARRIER_WAIT_PARITY(sb + S_FULLL + 8 * (p & 3), (p >> 2) & 1);
            MBARRIER_ARRIVE_RANK0(sb + S_FULLC + 8 * (p & 3));
        }
    } else if (wid == 5) {
        // =================== MMA ISSUE LANE (rank 0 only) ===================
        if (rank == 0 && elect_one_pred()) {
            for (int w = 0; w < nwork; w++) {
                MBARRIER_WAIT_PARITY_CLU(sb + S_AFULLC, w & 1);   // A ready, both CTAs
                for (int tile = 0; tile < 8; tile++) {
                    const int tt = w * 8 + tile;
                    if (tt >= 1)
                        MBARRIER_WAIT_PARITY_CLU(sb + S_EDONE, (tt - 1) & 1);
                    for (int kc = 0; kc < 8; kc++) {
                        const int kb = tt * 8 + kc;
                        const int s  = kb & 3;
                        MBARRIER_WAIT_PARITY_CLU(sb + S_FULLC + 8 * s, (kb >> 2) & 1);
                        TCGEN05_FENCE_AFTER();
                        const uint64_t ad = MAKE_SMEM_DESC(sb + S_A + (uint32_t)kc * 16384u);
                        const uint64_t bd = MAKE_SMEM_DESC(sb + S_B + (uint32_t)s * B_STAGE_BYTES);
#pragma unroll
                        for (int ks = 0; ks < 4; ks++)     // 4 x K32 per 128-chunk
                            mma_mxf8_ss_cg2(tmem, ad + ks * 2, bd + ks * 2,
                                            mxf8_idesc(ks),
                                            tmem + 256, tmem + 260,
                                            (uint32_t)((kc | ks) != 0));
                        TCGEN05_COMMIT_MC_CG2(sb + S_EMPTY + 8 * s, 0x3);
                    }
                    TCGEN05_COMMIT_MC_CG2(sb + S_DONE, 0x3);
                }
                TCGEN05_COMMIT_MC_CG2(sb + S_AEMPTY, 0x3);   // all item MMAs done
            }
        }
    } else {
        // =================== EPILOGUE WARPS (0-3) ===================
        float zacc[4] = {0.f, 0.f, 0.f, 0.f};

        for (int tt = 0; tt < NTT; tt++) {
            MBARRIER_WAIT_PARITY(sb + S_DONE, tt & 1);
            TCGEN05_FENCE_AFTER();

            uint32_t bufA[32], bufB[32];
            TCGEN05_LD_32X32B_X32(bufA, tmem + 0);
            TCGEN05_WAIT_LD();
#pragma unroll
            for (int ch = 0; ch < 8; ch++) {
                if (ch < 7) {          // prefetch next chunk while consuming current
                    if (ch & 1) { TCGEN05_LD_32X32B_X32(bufA, tmem + (ch + 1) * 32); }
                    else        { TCGEN05_LD_32X32B_X32(bufB, tmem + (ch + 1) * 32); }
                }
                const uint32_t* cur = (ch & 1) ? bufB : bufA;
                const int nb = (tt & 7) * TILE_N + ch * 32;
#pragma unroll
                for (int c = 0; c < 32; c++) {
                    float h = fmaf(__uint_as_float(cur[c]), INV_SCALE, s_b1[nb + c]);
                    h = fmaxf(h, 0.f);
                    zacc[c & 3] = fmaf(h, s_w2[nb + c], zacc[c & 3]);
                }
                if (ch < 7) TCGEN05_WAIT_LD();
            }
            TCGEN05_FENCE_BEFORE();
            NAMED_BAR(2, 128);          // all 4 epilogue warps done reading D
            if (tid == 0) MBARRIER_ARRIVE_RANK0(sb + S_EDONE);

            if ((tt & 7) == 7) {
                // ---- end of work item: emit z, reset, load next b1/W2 ----
                const int w  = tt >> 3;
                const int wk = cid + N_CLUSTERS * w;
                const int e_w = wk >> 5;
                const int m0w = (wk & 31) * 256 + (int)rank * 128;
                const float z = (zacc[0] + zacc[1]) + (zacc[2] + zacc[3]);
                g_zbuf[(size_t)e_w * BATCH_SZ + m0w + tid] = z;
                zacc[0] = zacc[1] = zacc[2] = zacc[3] = 0.f;

                if (w + 1 < nwork) {
                    const int e_n = (cid + N_CLUSTERS * (w + 1)) >> 5;
                    for (int i = tid; i < HID; i += 128) {
                        s_b1[i] = __ldg(b1 + (size_t)e_n * HID + i);
                        s_w2[i] = __ldg(W2 + (size_t)e_n * HID + i);
                    }
                }
                NAMED_BAR(2, 128);      // reload visible before next epilogue
            }
        }
    }

    __syncthreads();
    if (wid == 0) {
        TCGEN05_RELINQUISH_CG2();
        TCGEN05_DEALLOC_CG2(tmem, 512);
    }
    CLUSTER_SYNC();   // peer MMAs/multicasts targeting our SMEM must be done
#endif  // TC_OK
}

// ---------------------------------------------------------------------------
// Host/device shared swizzle
// ---------------------------------------------------------------------------
__device__ __forceinline__ uint32_t swz128(uint32_t o) {
    return o ^ ((o >> 3) & 0x70);
}

// x fp32 [B][K] -> g_xa fp8 blobs (scaled by 2^6); 16 k per thread.
__global__ void cvt_x_kernel(const float* __restrict__ x) {
    const int i = blockIdx.x * blockDim.x + threadIdx.x;   // < 8192*64
    const int m = i >> 6;
    const int g = i & 63;               // 16B group; kc = g>>3
    const float* src = x + (size_t)m * IN_SZ + g * 16;
    float v[16];
#pragma unroll
    for (int j = 0; j < 16; j++) v[j] = src[j] * X_SCALE;
    uint32_t w[4];
#pragma unroll
    for (int q = 0; q < 4; q++) {
        const uint16_t p01 = f2e4m3x2(v[4 * q + 0], v[4 * q + 1]);
        const uint16_t p23 = f2e4m3x2(v[4 * q + 2], v[4 * q + 3]);
        w[q] = (uint32_t)p01 | ((uint32_t)p23 << 16);
    }
    uint4 out = make_uint4(w[0], w[1], w[2], w[3]);
    const int mb = m >> 7, r = m & 127, kc = g >> 3;
    const uint32_t off = swz128((uint32_t)(r * 128 + (g & 7) * 16));
    *(uint4*)((char*)g_xa + (((size_t)(mb * 8 + kc)) << 14) + off) = out;
}

// W1 fp32 [E][K][H] -> g_wb fp8 16KB blobs (scaled by 2^13), K-major.
// blob(e, nt8, rank, kc8): row = hid&127, rank=(hid>>7)&1, nt=hid>>8.
__global__ void cvt_w1_kernel(const float* __restrict__ W1) {
    __shared__ float tile[128][33];
    const int e  = blockIdx.z;
    const int kc = blockIdx.y;          // K-chunk of 128
    const int hb = blockIdx.x;          // hid block of 32
    const int t  = threadIdx.x;         // 0..255
    const float* src = W1 + ((size_t)e * IN_SZ + kc * 128) * HID + hb * 32;
#pragma unroll
    for (int it = 0; it < 16; it++) {
        const int lin = it * 256 + t;   // < 4096 = 128k x 32h
        const int kr = lin >> 5, hc = lin & 31;
        tile[kr][hc] = src[(size_t)kr * HID + hc];
    }
    __syncthreads();
    const int h = t >> 3, g = t & 7;    // h: 0..31, g: 16B group 0..7
    float v[16];
#pragma unroll
    for (int j = 0; j < 16; j++) v[j] = tile[g * 16 + j][h] * W_SCALE;
    uint32_t w[4];
#pragma unroll
    for (int q = 0; q < 4; q++) {
        const uint16_t p01 = f2e4m3x2(v[4 * q + 0], v[4 * q + 1]);
        const uint16_t p23 = f2e4m3x2(v[4 * q + 2], v[4 * q + 3]);
        w[q] = (uint32_t)p01 | ((uint32_t)p23 << 16);
    }
    uint4 out = make_uint4(w[0], w[1], w[2], w[3]);
    const int hid = hb * 32 + h;
    const int nt  = hid >> 8;           // 256-col N tile
    const int rk  = (hid >> 7) & 1;
    const int row = hid & 127;
    const size_t blob = (size_t)(e * 128 + nt * 16 + rk * 8 + kc);
    const uint32_t off = swz128((uint32_t)(row * 128 + g * 16));
    *(uint4*)((char*)g_wb + (blob << 14) + off) = out;
}

// ---------------------------------------------------------------------------
// Final reduce: out[m] = mean_e sigmoid(z[e][m] + b2[e]); 4 threads/output
// ---------------------------------------------------------------------------
__global__ void reduce_kernel(const float* __restrict__ b2, float* __restrict__ out) {
    const int tid = blockIdx.x * blockDim.x + threadIdx.x;  // < 32768
    const int i = tid >> 2, l = tid & 3;
    float s = 0.f;
#pragma unroll
    for (int ex = l; ex < N_EXPERTS; ex += 4) {
        const float z = g_zbuf[(size_t)ex * BATCH_SZ + i] + b2[ex];
        s += 1.f / (1.f + __expf(-z));
    }
    s += __shfl_xor_sync(0xFFFFFFFFu, s, 1);
    s += __shfl_xor_sync(0xFFFFFFFFu, s, 2);
    if (l == 0) out[i] = s * (1.f / N_EXPERTS);
}

// ---------------------------------------------------------------------------
// Harness entry
// ---------------------------------------------------------------------------
extern "C" void kernel_launch(void* const* d_in, const int* in_sizes, int n_in,
                              void* d_out, int out_size) {
    (void)in_sizes; (void)n_in; (void)out_size;
    const float* x  = (const float*)d_in[0];
    const float* W1 = (const float*)d_in[1];
    const float* b1 = (const float*)d_in[2];
    const float* W2 = (const float*)d_in[3];
    const float* b2 = (const float*)d_in[4];
    float* out = (float*)d_out;

    cudaFuncSetAttribute(gemm_fused, cudaFuncAttributeMaxDynamicSharedMemorySize,
                         (int)SMEM_BYTES);

    cvt_x_kernel<<<(BATCH_SZ * 64) / 256, 256>>>(x);

    dim3 tg(HID / 32, IN_SZ / 128, N_EXPERTS);   // (hb, kc, e)
    cvt_w1_kernel<<<tg, 256>>>(W1);

    // persistent: 148 CTAs = 74 cg2 clusters
    gemm_fused<<<2 * N_CLUSTERS, 192, SMEM_BYTES>>>(b1, W2);

    reduce_kernel<<<(BATCH_SZ * 4) / 256, 256>>>(b2, out);
}

// round 16
// speedup vs baseline: 1.5082x; 1.1696x over previous
#include <cuda_runtime.h>
#include <cuda_bf16.h>
#include <cstdint>

// ---------------------------------------------------------------------------
// Arch gate: tcgen05 is sm_103a-ONLY (plain compute_103 phase must compile).
// ---------------------------------------------------------------------------
#if defined(__CUDA_ARCH__) && (__CUDA_ARCH__ == 1030) && defined(__CUDA_ARCH_FEAT_SM103_ALL)
#define TC_OK 1
#else
#define TC_OK 0
#endif

// ---------------------------------------------------------------------------
// Problem constants
// ---------------------------------------------------------------------------
#define N_EXPERTS 30
#define IN_SZ     1024
#define HID       2048
#define BATCH_SZ  8192

#define N_CLUSTERS 74            // 148 CTAs / 2
#define N_WORK     960           // 30 experts * 32 m-blocks of 256

// Exact power-of-2 operand scaling (folded out in epilogue)
#define X_SCALE   64.0f          // 2^6:  |x|max ~5.4 -> ~350 < 448
#define W_SCALE   8192.0f        // 2^13: |w|max 1/32 -> 256 < 448
#define INV_SCALE 1.9073486328125e-6f   // 2^-19 exact

// ---------------------------------------------------------------------------
// Device scratch (fp8 e4m3 blobs, SW128-swizzled SMEM images).
// g_xa: A blob(mb128, kc8) = 16KB: x rows [mb*128,+128), k [kc*128,+128).
//       kc-contiguous -> one m-block's full A = 128KB contiguous.
// g_wb: B blob(e, nt8, rank, kc8) = 16KB: 128 n-rows x 128B where
//       hid = nt*256 + rank*128 + row, k [kc*128,+128).
// ---------------------------------------------------------------------------
__device__ __align__(16) uint8_t g_xa[(size_t)BATCH_SZ * IN_SZ];                 // 8 MB
__device__ __align__(16) uint8_t g_wb[(size_t)N_EXPERTS * HID * IN_SZ];          // 63 MB
__device__ float g_zbuf[(size_t)N_EXPERTS * BATCH_SZ];                            // 1 MB

// ---------------------------------------------------------------------------
// PTX helpers
// ---------------------------------------------------------------------------
__device__ __forceinline__ uint32_t smem_to_u32(const void* p) {
    uint32_t a;
    asm("{ .reg .u64 t; cvta.to.shared.u64 t, %1; cvt.u32.u64 %0, t; }"
        : "=r"(a) : "l"(p));
    return a;
}

__device__ __forceinline__ uint32_t elect_one_pred() {
    uint32_t pred;
    asm volatile(
        "{\n\t.reg .pred p;\n\telect.sync _|p, 0xFFFFFFFF;\n\tselp.b32 %0, 1, 0, p;\n\t}"
        : "=r"(pred));
    return pred;
}

__device__ __forceinline__ uint32_t cluster_rank() {
    uint32_t r;
    asm("mov.u32 %0, %%cluster_ctarank;" : "=r"(r));
    return r;
}

#define MBARRIER_INIT(addr, cnt) \
    asm volatile("mbarrier.init.shared.b64 [%0], %1;" :: "r"((uint32_t)(addr)), "r"((uint32_t)(cnt)) : "memory")

#define MBARRIER_EXPECT_TX(addr, bytes) \
    asm volatile("mbarrier.arrive.expect_tx.shared.b64 _, [%0], %1;" \
        :: "r"((uint32_t)(addr)), "r"((uint32_t)(bytes)) : "memory")

// local wait, acquire at cta scope
#define MBARRIER_WAIT_PARITY(mbar_smem_addr, phase_parity) do { \
    uint32_t _mbar = (uint32_t)(mbar_smem_addr); \
    uint32_t _parity = (uint32_t)(phase_parity); \
    uint32_t _done; \
    asm volatile( \
        "{\n\t.reg .pred p;\n\t" \
        "mbarrier.try_wait.parity.acquire.cta.shared::cta.b64 p, [%1], %2;\n\t" \
        "selp.b32 %0, 1, 0, p;\n\t}" \
        : "=r"(_done) : "r"(_mbar), "r"(_parity) : "memory"); \
    if (!_done) { \
        asm volatile( \
            "{\n\t.reg .pred P1;\n\t" \
            "WAIT_LOOP_%=:\n\t" \
            "mbarrier.try_wait.parity.acquire.cta.shared::cta.b64 P1, [%0], %1, 0x989680;\n\t" \
            "@P1 bra.uni WAIT_DONE_%=;\n\t" \
            "bra.uni WAIT_LOOP_%=;\n\t" \
            "WAIT_DONE_%=:\n\t}" \
            :: "r"(_mbar), "r"(_parity) : "memory"); \
    } \
} while (0)

// cluster-scope acquire wait (peer-signaled barriers / peer data)
#define MBARRIER_WAIT_PARITY_CLU(mbar_smem_addr, phase_parity) do { \
    uint32_t _mbar = (uint32_t)(mbar_smem_addr); \
    uint32_t _parity = (uint32_t)(phase_parity); \
    uint32_t _done; \
    asm volatile( \
        "{\n\t.reg .pred p;\n\t" \
        "mbarrier.try_wait.parity.acquire.cluster.shared::cta.b64 p, [%1], %2;\n\t" \
        "selp.b32 %0, 1, 0, p;\n\t}" \
        : "=r"(_done) : "r"(_mbar), "r"(_parity) : "memory"); \
    if (!_done) { \
        asm volatile( \
            "{\n\t.reg .pred P1;\n\t" \
            "WAIT_LOOP_%=:\n\t" \
            "mbarrier.try_wait.parity.acquire.cluster.shared::cta.b64 P1, [%0], %1, 0x989680;\n\t" \
            "@P1 bra.uni WAIT_DONE_%=;\n\t" \
            "bra.uni WAIT_LOOP_%=;\n\t" \
            "WAIT_DONE_%=:\n\t}" \
            :: "r"(_mbar), "r"(_parity) : "memory"); \
    } \
} while (0)

// arrive on the same-offset mbarrier in cluster rank 0
#define MBARRIER_ARRIVE_RANK0(local_mbar_addr) \
    asm volatile( \
        "{\n\t.reg .b32 remAddr32;\n\t" \
        "mapa.shared::cluster.u32 remAddr32, %0, 0;\n\t" \
        "mbarrier.arrive.shared::cluster.b64 _, [remAddr32];\n\t}" \
        :: "r"((uint32_t)(local_mbar_addr)) : "memory")

#define CLUSTER_SYNC() do { \
    asm volatile("barrier.cluster.arrive.aligned;" ::: "memory"); \
    asm volatile("barrier.cluster.wait.aligned;" ::: "memory"); \
} while (0)

#define NAMED_BAR(id, cnt) \
    asm volatile("bar.sync %0, %1;" :: "r"(id), "r"(cnt) : "memory")

// bulk async copy global -> own-CTA shared, completion on LOCAL mbarrier
#define CP_BULK_G2S(dst_smem, src_gmem, bytes, mbar) \
    asm volatile("cp.async.bulk.shared::cluster.global.mbarrier::complete_tx::bytes " \
                 "[%0], [%1], %2, [%3];" \
        :: "r"((uint32_t)(dst_smem)), "l"(src_gmem), "r"((uint32_t)(bytes)), \
           "r"((uint32_t)(mbar)) : "memory")

// pack two floats to e4m3x2
__device__ __forceinline__ uint16_t f2e4m3x2(float lo, float hi) {
    uint16_t r;
    asm("cvt.rn.satfinite.e4m3x2.f32 %0, %1, %2;" : "=h"(r) : "f"(hi), "f"(lo));
    return r;
}

#if TC_OK
#define TCGEN05_ALLOC_CG2(smem_result_addr, nCols) \
    asm volatile("tcgen05.alloc.cta_group::2.sync.aligned.shared::cta.b32 [%0], %1;" \
        :: "r"((uint32_t)(smem_result_addr)), "r"((uint32_t)(nCols)) : "memory")

#define TCGEN05_DEALLOC_CG2(tmem_addr, nCols) \
    asm volatile("tcgen05.dealloc.cta_group::2.sync.aligned.b32 %0, %1;" \
        :: "r"(tmem_addr), "r"((uint32_t)(nCols)))

#define TCGEN05_RELINQUISH_CG2() \
    asm volatile("tcgen05.relinquish_alloc_permit.cta_group::2.sync.aligned;")

#define TCGEN05_COMMIT_MC_CG2(mbar_smem_addr, cta_mask) \
    asm volatile("tcgen05.commit.cta_group::2.mbarrier::arrive::one.shared::cluster.multicast::cluster.b64 [%0], %1;" \
        :: "r"((uint32_t)(mbar_smem_addr)), "h"((uint16_t)(cta_mask)) : "memory")

#define TCGEN05_WAIT_LD()  asm volatile("tcgen05.wait::ld.sync.aligned;" ::: "memory")
#define TCGEN05_FENCE_BEFORE() asm volatile("tcgen05.fence::before_thread_sync;" ::: "memory")
#define TCGEN05_FENCE_AFTER()  asm volatile("tcgen05.fence::after_thread_sync;" ::: "memory")

#define TCGEN05_LD_32X32B_X32(r, tmem_addr) \
    asm volatile( \
        "tcgen05.ld.sync.aligned.32x32b.x32.b32 " \
        "{%0, %1, %2, %3, %4, %5, %6, %7, " \
        " %8, %9, %10, %11, %12, %13, %14, %15, " \
        " %16, %17, %18, %19, %20, %21, %22, %23, " \
        " %24, %25, %26, %27, %28, %29, %30, %31}, [%32];" \
        : "=r"((r)[0]),  "=r"((r)[1]),  "=r"((r)[2]),  "=r"((r)[3]), \
          "=r"((r)[4]),  "=r"((r)[5]),  "=r"((r)[6]),  "=r"((r)[7]), \
          "=r"((r)[8]),  "=r"((r)[9]),  "=r"((r)[10]), "=r"((r)[11]), \
          "=r"((r)[12]), "=r"((r)[13]), "=r"((r)[14]), "=r"((r)[15]), \
          "=r"((r)[16]), "=r"((r)[17]), "=r"((r)[18]), "=r"((r)[19]), \
          "=r"((r)[20]), "=r"((r)[21]), "=r"((r)[22]), "=r"((r)[23]), \
          "=r"((r)[24]), "=r"((r)[25]), "=r"((r)[26]), "=r"((r)[27]), \
          "=r"((r)[28]), "=r"((r)[29]), "=r"((r)[30]), "=r"((r)[31]) \
        : "r"(tmem_addr))

// SW128 K-major SMEM descriptor (layout=SW128, Blackwell version=1, LBO=1, SBO=64)
static constexpr uint64_t SMEM_DESC_BASE_SW128 =
    (uint64_t(2) << 61) | (uint64_t(1) << 46) | (uint64_t(64) << 32) | (uint64_t(1) << 16);
#define MAKE_SMEM_DESC(base_addr) \
    (SMEM_DESC_BASE_SW128 | ((uint64_t)((base_addr) >> 4) & 0x3FFF))

// idesc for cta_group::2 kind::f8f6f4 (plain fp8, no block scale):
// dtype=F32 (bit4), atype=E4M3 (0 @[7:9]), btype=E4M3 (0 @[10:12]),
// N/8 @[17:23], M/16 @[24:29].  (M-field cross-checked: 16<<24 == 2<<27,
// the exact value the working mxf8 kernel used for M=256.)
static constexpr uint32_t IDESC_F8 =
    (1u << 4) | ((256u / 8) << 17) | ((256u / 16) << 24);

// cg2 fp8 SS MMA, fp32 D, no scales: same operand shape as proven kind::f16 cg2
__device__ __forceinline__ void mma_f8_ss_cg2(uint32_t d, uint64_t ad, uint64_t bd,
                                              uint32_t idesc, uint32_t acc) {
    asm volatile(
        "{\n\t.reg .pred p;\n\tsetp.ne.u32 p, %5, 0;\n\t"
        "tcgen05.mma.cta_group::2.kind::f8f6f4 [%0], %1, %2, %3, "
        "{%4, %4, %4, %4, %4, %4, %4, %4}, p;\n\t}"
        :: "r"(d), "l"(ad), "l"(bd), "r"(idesc), "r"(0u), "r"(acc) : "memory");
}
#endif  // TC_OK

// ---------------------------------------------------------------------------
// Persistent cg2 FP8 GEMM: A-resident + D PING-PONG (scales gone -> both
// 256-col D buffers fit the 512-col TMEM).
// Tile = 256 rows x 256 cols; K-chunk = 128; 8 tiles x 8 chunks = 64/item.
// 192 threads: w0-3 epilogue, w4 producer lane, w5 MMA-issue lane (rank0).
// Item boundary ordering (R14/R15-proven): flush pending B relay -> wait
// AEMPTY -> load A. In-loop relays only for j >= 1.
// ---------------------------------------------------------------------------
static constexpr int TILE_N   = 256;
static constexpr int STAGES   = 4;

static constexpr uint32_t S_TMEM   = 0;
static constexpr uint32_t S_AFULLL = 16;                 // per CTA, tx 128KB
static constexpr uint32_t S_AFULLC = 24;                 // rank0, cnt=2
static constexpr uint32_t S_AEMPTY = 32;                 // per CTA (commit-mc)
static constexpr uint32_t S_FULLL  = 40;                 // 4 x 8B per CTA (tx 16KB)
static constexpr uint32_t S_FULLC  = 72;                 // 4 x 8B rank0 (cnt=2)
static constexpr uint32_t S_EMPTY  = 104;                // 4 x 8B per CTA (cnt=1)
static constexpr uint32_t S_DONE0  = 136;                // per CTA (commit-mc)
static constexpr uint32_t S_DONE1  = 144;
static constexpr uint32_t S_EDONE0 = 152;                // rank0, cnt=2
static constexpr uint32_t S_EDONE1 = 160;
static constexpr uint32_t S_B1     = 1024;
static constexpr uint32_t S_W2     = 1024 + 4 * HID;         // 9216
static constexpr uint32_t S_A      = S_W2 + 4 * HID;         // 17408 (1024-aligned)
static constexpr uint32_t A_BYTES  = 131072;                 // 128 rows x 1024 k fp8
static constexpr uint32_t S_B      = S_A + A_BYTES;          // 148480
static constexpr uint32_t B_STAGE_BYTES = 16384;             // 128 n-rows x 128 B
static constexpr uint32_t SMEM_BYTES = S_B + STAGES * B_STAGE_BYTES; // 214016

__global__ void __launch_bounds__(192, 1) __cluster_dims__(2, 1, 1)
gemm_fused(const float* __restrict__ b1, const float* __restrict__ W2) {
#if TC_OK
    extern __shared__ __align__(1024) uint8_t smem[];
    const uint32_t sb = smem_to_u32(smem);
    const int tid  = threadIdx.x;
    const int wid  = tid >> 5;
    const uint32_t rank = cluster_rank();
    const int cid  = blockIdx.x >> 1;              // cluster id 0..73

    const int nwork = (N_WORK - cid + N_CLUSTERS - 1) / N_CLUSTERS;  // 13 or 12
    const int KKT   = nwork * 64;                  // total B chunks, flat
    const int NTT   = nwork * 8;                   // total 256-col tiles, flat

    if (wid == 0) TCGEN05_ALLOC_CG2(sb + S_TMEM, 512);
    if (tid == 0) {
        if (rank == 0) {
            MBARRIER_INIT(sb + S_AFULLC, 2);
            for (int s = 0; s < STAGES; s++) MBARRIER_INIT(sb + S_FULLC + 8 * s, 2);
            MBARRIER_INIT(sb + S_EDONE0, 2);
            MBARRIER_INIT(sb + S_EDONE1, 2);
        }
        MBARRIER_INIT(sb + S_AFULLL, 1);
        MBARRIER_INIT(sb + S_AEMPTY, 1);
        for (int s = 0; s < STAGES; s++) {
            MBARRIER_INIT(sb + S_FULLL + 8 * s, 1);   // expect_tx arms each phase
            MBARRIER_INIT(sb + S_EMPTY + 8 * s, 1);
        }
        MBARRIER_INIT(sb + S_DONE0, 1);
        MBARRIER_INIT(sb + S_DONE1, 1);
    }
    __syncthreads();

    uint32_t tmem;
    asm volatile("ld.shared.b32 %0, [%1];" : "=r"(tmem) : "r"(sb + S_TMEM));

    float* s_b1 = (float*)(smem + S_B1);
    float* s_w2 = (float*)(smem + S_W2);
    if (tid < 128) {
        const int e0 = cid >> 5;
        for (int i = tid; i < HID; i += 128) {
            s_b1[i] = __ldg(b1 + (size_t)e0 * HID + i);
            s_w2[i] = __ldg(W2 + (size_t)e0 * HID + i);
        }
    }
    __syncthreads();
    CLUSTER_SYNC();   // barriers ready cluster-wide before any arrival/tx

    if (wid == 4) {
        // =================== PRODUCER LANE (both CTAs) ===================
        if (elect_one_pred()) {
            const char* xa = (const char*)g_xa;
            const char* wb = (const char*)g_wb;

            for (int w = 0; w < nwork; w++) {
                const int wk = cid + N_CLUSTERS * w;
                const int e_w = wk >> 5;
                const int mb  = (wk & 31) * 2 + (int)rank;   // m-block of 128

                // ---- item boundary: FLUSH pending relay, THEN wait AEMPTY ----
                if (w >= 1) {
                    const int p = w * 64 - 1;     // last chunk of previous item
                    MBARRIER_WAIT_PARITY(sb + S_FULLL + 8 * (p & 3), (p >> 2) & 1);
                    MBARRIER_ARRIVE_RANK0(sb + S_FULLC + 8 * (p & 3));
                    MBARRIER_WAIT_PARITY(sb + S_AEMPTY, (w - 1) & 1);
                }

                // ---- A: 128KB resident, 8 bulks, 1 tx barrier ----
                MBARRIER_EXPECT_TX(sb + S_AFULLL, A_BYTES);
                const char* asrc = xa + ((size_t)mb << 17);
#pragma unroll
                for (int kc = 0; kc < 8; kc++)
                    CP_BULK_G2S(sb + S_A + (uint32_t)kc * 16384u,
                                asrc + ((size_t)kc << 14), 16384, sb + S_AFULLL);

                // ---- B: 64 chunks of 16KB through the ring ----
                for (int j = 0; j < 64; j++) {
                    const int la = w * 64 + j;
                    const int s  = la & 3;
                    const int u  = la >> 2;
                    if (u >= 1)
                        MBARRIER_WAIT_PARITY(sb + S_EMPTY + 8 * s, (u - 1) & 1);

                    const int nt = j >> 3;        // N-tile of 256
                    const int kc = j & 7;         // K-chunk of 128
                    MBARRIER_EXPECT_TX(sb + S_FULLL + 8 * s, B_STAGE_BYTES);
                    const size_t boff =
                        ((size_t)(e_w * 128 + nt * 16 + (int)rank * 8 + kc)) << 14;
                    CP_BULK_G2S(sb + S_B + (uint32_t)s * B_STAGE_BYTES,
                                wb + boff, B_STAGE_BYTES, sb + S_FULLL + 8 * s);

                    // relay previous B chunk (within-item; j==0 handled at boundary)
                    if (j >= 1) {
                        const int p = la - 1;
                        MBARRIER_WAIT_PARITY(sb + S_FULLL + 8 * (p & 3), (p >> 2) & 1);
                        MBARRIER_ARRIVE_RANK0(sb + S_FULLC + 8 * (p & 3));
                    }
                    // relay A completion once, early in the item
                    if (j == 1) {
                        MBARRIER_WAIT_PARITY(sb + S_AFULLL, w & 1);
                        MBARRIER_ARRIVE_RANK0(sb + S_AFULLC);
                    }
                }
            }
            // relay final B chunk
            const int p = KKT - 1;
            MBARRIER_WAIT_PARITY(sb + S_FULLL + 8 * (p & 3), (p >> 2) & 1);
            MBARRIER_ARRIVE_RANK0(sb + S_FULLC + 8 * (p & 3));
        }
    } else if (wid == 5) {
        // =================== MMA ISSUE LANE (rank 0 only) ===================
        if (rank == 0 && elect_one_pred()) {
            for (int w = 0; w < nwork; w++) {
                MBARRIER_WAIT_PARITY_CLU(sb + S_AFULLC, w & 1);   // A ready, both CTAs
                for (int tile = 0; tile < 8; tile++) {
                    const int tt  = w * 8 + tile;
                    const int buf = tt & 1;
                    const uint32_t dbase = tmem + (uint32_t)buf * 256;
                    if (tt >= 2)                  // buffer reuse: epilogue done
                        MBARRIER_WAIT_PARITY_CLU(sb + (buf ? S_EDONE1 : S_EDONE0),
                                                 ((tt >> 1) - 1) & 1);
                    for (int kc = 0; kc < 8; kc++) {
                        const int kb = tt * 8 + kc;
                        const int s  = kb & 3;
                        MBARRIER_WAIT_PARITY_CLU(sb + S_FULLC + 8 * s, (kb >> 2) & 1);
                        TCGEN05_FENCE_AFTER();
                        const uint64_t ad = MAKE_SMEM_DESC(sb + S_A + (uint32_t)kc * 16384u);
                        const uint64_t bd = MAKE_SMEM_DESC(sb + S_B + (uint32_t)s * B_STAGE_BYTES);
#pragma unroll
                        for (int ks = 0; ks < 4; ks++)     // 4 x K32 per 128-chunk
                            mma_f8_ss_cg2(dbase, ad + ks * 2, bd + ks * 2,
                                          IDESC_F8, (uint32_t)((kc | ks) != 0));
                        TCGEN05_COMMIT_MC_CG2(sb + S_EMPTY + 8 * s, 0x3);
                    }
                    TCGEN05_COMMIT_MC_CG2(sb + (buf ? S_DONE1 : S_DONE0), 0x3);
                }
                TCGEN05_COMMIT_MC_CG2(sb + S_AEMPTY, 0x3);   // all item MMAs done
            }
        }
    } else {
        // =================== EPILOGUE WARPS (0-3) ===================
        float zacc[4] = {0.f, 0.f, 0.f, 0.f};

        for (int tt = 0; tt < NTT; tt++) {
            const int buf = tt & 1;
            const uint32_t dbase = tmem + (uint32_t)buf * 256;
            MBARRIER_WAIT_PARITY(sb + (buf ? S_DONE1 : S_DONE0), (tt >> 1) & 1);
            TCGEN05_FENCE_AFTER();

            uint32_t bufA[32], bufB[32];
            TCGEN05_LD_32X32B_X32(bufA, dbase);
            TCGEN05_WAIT_LD();
#pragma unroll
            for (int ch = 0; ch < 8; ch++) {
                if (ch < 7) {          // prefetch next chunk while consuming current
                    if (ch & 1) { TCGEN05_LD_32X32B_X32(bufA, dbase + (ch + 1) * 32); }
                    else        { TCGEN05_LD_32X32B_X32(bufB, dbase + (ch + 1) * 32); }
                }
                const uint32_t* cur = (ch & 1) ? bufB : bufA;
                const int nb = (tt & 7) * TILE_N + ch * 32;
#pragma unroll
                for (int c = 0; c < 32; c++) {
                    float h = fmaf(__uint_as_float(cur[c]), INV_SCALE, s_b1[nb + c]);
                    h = fmaxf(h, 0.f);
                    zacc[c & 3] = fmaf(h, s_w2[nb + c], zacc[c & 3]);
                }
                if (ch < 7) TCGEN05_WAIT_LD();
            }
            TCGEN05_FENCE_BEFORE();
            NAMED_BAR(2, 128);          // all 4 epilogue warps done with this buf
            if (tid == 0) MBARRIER_ARRIVE_RANK0(sb + (buf ? S_EDONE1 : S_EDONE0));

            if ((tt & 7) == 7) {
                // ---- end of work item: emit z, reset, load next b1/W2 ----
                const int w  = tt >> 3;
                const int wk = cid + N_CLUSTERS * w;
                const int e_w = wk >> 5;
                const int m0w = (wk & 31) * 256 + (int)rank * 128;
                const float z = (zacc[0] + zacc[1]) + (zacc[2] + zacc[3]);
                g_zbuf[(size_t)e_w * BATCH_SZ + m0w + tid] = z;
                zacc[0] = zacc[1] = zacc[2] = zacc[3] = 0.f;

                if (w + 1 < nwork) {
                    const int e_n = (cid + N_CLUSTERS * (w + 1)) >> 5;
                    for (int i = tid; i < HID; i += 128) {
                        s_b1[i] = __ldg(b1 + (size_t)e_n * HID + i);
                        s_w2[i] = __ldg(W2 + (size_t)e_n * HID + i);
                    }
                }
                NAMED_BAR(2, 128);      // reload visible before next epilogue
            }
        }
    }

    __syncthreads();
    if (wid == 0) {
        TCGEN05_RELINQUISH_CG2();
        TCGEN05_DEALLOC_CG2(tmem, 512);
    }
    CLUSTER_SYNC();   // peer MMAs/multicasts targeting our SMEM must be done
#endif  // TC_OK
}

// ---------------------------------------------------------------------------
// Host/device shared swizzle
// ---------------------------------------------------------------------------
__device__ __forceinline__ uint32_t swz128(uint32_t o) {
    return o ^ ((o >> 3) & 0x70);
}

// x fp32 [B][K] -> g_xa fp8 blobs (scaled by 2^6); 16 k per thread.
__global__ void cvt_x_kernel(const float* __restrict__ x) {
    const int i = blockIdx.x * blockDim.x + threadIdx.x;   // < 8192*64
    const int m = i >> 6;
    const int g = i & 63;               // 16B group; kc = g>>3
    const float* src = x + (size_t)m * IN_SZ + g * 16;
    float v[16];
#pragma unroll
    for (int j = 0; j < 16; j++) v[j] = src[j] * X_SCALE;
    uint32_t w[4];
#pragma unroll
    for (int q = 0; q < 4; q++) {
        const uint16_t p01 = f2e4m3x2(v[4 * q + 0], v[4 * q + 1]);
        const uint16_t p23 = f2e4m3x2(v[4 * q + 2], v[4 * q + 3]);
        w[q] = (uint32_t)p01 | ((uint32_t)p23 << 16);
    }
    uint4 out = make_uint4(w[0], w[1], w[2], w[3]);
    const int mb = m >> 7, r = m & 127, kc = g >> 3;
    const uint32_t off = swz128((uint32_t)(r * 128 + (g & 7) * 16));
    *(uint4*)((char*)g_xa + (((size_t)(mb * 8 + kc)) << 14) + off) = out;
}

// W1 fp32 [E][K][H] -> g_wb fp8 16KB blobs (scaled by 2^13), K-major.
// blob(e, nt8, rank, kc8): row = hid&127, rank=(hid>>7)&1, nt=hid>>8.
__global__ void cvt_w1_kernel(const float* __restrict__ W1) {
    __shared__ float tile[128][33];
    const int e  = blockIdx.z;
    const int kc = blockIdx.y;          // K-chunk of 128
    const int hb = blockIdx.x;          // hid block of 32
    const int t  = threadIdx.x;         // 0..255
    const float* src = W1 + ((size_t)e * IN_SZ + kc * 128) * HID + hb * 32;
#pragma unroll
    for (int it = 0; it < 16; it++) {
        const int lin = it * 256 + t;   // < 4096 = 128k x 32h
        const int kr = lin >> 5, hc = lin & 31;
        tile[kr][hc] = src[(size_t)kr * HID + hc];
    }
    __syncthreads();
    const int h = t >> 3, g = t & 7;    // h: 0..31, g: 16B group 0..7
    float v[16];
#pragma unroll
    for (int j = 0; j < 16; j++) v[j] = tile[g * 16 + j][h] * W_SCALE;
    uint32_t w[4];
#pragma unroll
    for (int q = 0; q < 4; q++) {
        const uint16_t p01 = f2e4m3x2(v[4 * q + 0], v[4 * q + 1]);
        const uint16_t p23 = f2e4m3x2(v[4 * q + 2], v[4 * q + 3]);
        w[q] = (uint32_t)p01 | ((uint32_t)p23 << 16);
    }
    uint4 out = make_uint4(w[0], w[1], w[2], w[3]);
    const int hid = hb * 32 + h;
    const int nt  = hid >> 8;           // 256-col N tile
    const int rk  = (hid >> 7) & 1;
    const int row = hid & 127;
    const size_t blob = (size_t)(e * 128 + nt * 16 + rk * 8 + kc);
    const uint32_t off = swz128((uint32_t)(row * 128 + g * 16));
    *(uint4*)((char*)g_wb + (blob << 14) + off) = out;
}

// ---------------------------------------------------------------------------
// Final reduce: out[m] = mean_e sigmoid(z[e][m] + b2[e]); 4 threads/output
// ---------------------------------------------------------------------------
__global__ void reduce_kernel(const float* __restrict__ b2, float* __restrict__ out) {
    const int tid = blockIdx.x * blockDim.x + threadIdx.x;  // < 32768
    const int i = tid >> 2, l = tid & 3;
    float s = 0.f;
#pragma unroll
    for (int ex = l; ex < N_EXPERTS; ex += 4) {
        const float z = g_zbuf[(size_t)ex * BATCH_SZ + i] + b2[ex];
        s += 1.f / (1.f + __expf(-z));
    }
    s += __shfl_xor_sync(0xFFFFFFFFu, s, 1);
    s += __shfl_xor_sync(0xFFFFFFFFu, s, 2);
    if (l == 0) out[i] = s * (1.f / N_EXPERTS);
}

// ---------------------------------------------------------------------------
// Harness entry
// ---------------------------------------------------------------------------
extern "C" void kernel_launch(void* const* d_in, const int* in_sizes, int n_in,
                              void* d_out, int out_size) {
    (void)in_sizes; (void)n_in; (void)out_size;
    const float* x  = (const float*)d_in[0];
    const float* W1 = (const float*)d_in[1];
    const float* b1 = (const float*)d_in[2];
    const float* W2 = (const float*)d_in[3];
    const float* b2 = (const float*)d_in[4];
    float* out = (float*)d_out;

    cudaFuncSetAttribute(gemm_fused, cudaFuncAttributeMaxDynamicSharedMemorySize,
                         (int)SMEM_BYTES);

    cvt_x_kernel<<<(BATCH_SZ * 64) / 256, 256>>>(x);

    dim3 tg(HID / 32, IN_SZ / 128, N_EXPERTS);   // (hb, kc, e)
    cvt_w1_kernel<<<tg, 256>>>(W1);

    // persistent: 148 CTAs = 74 cg2 clusters
    gemm_fused<<<2 * N_CLUSTERS, 192, SMEM_BYTES>>>(b1, W2);

    reduce_kernel<<<(BATCH_SZ * 4) / 256, 256>>>(b2, out);
}

// round 17
// speedup vs baseline: 1.5624x; 1.0360x over previous
#include <cuda_runtime.h>
#include <cuda_bf16.h>
#include <cstdint>

// ---------------------------------------------------------------------------
// Arch gate: tcgen05 is sm_103a-ONLY (plain compute_103 phase must compile).
// ---------------------------------------------------------------------------
#if defined(__CUDA_ARCH__) && (__CUDA_ARCH__ == 1030) && defined(__CUDA_ARCH_FEAT_SM103_ALL)
#define TC_OK 1
#else
#define TC_OK 0
#endif

// ---------------------------------------------------------------------------
// Problem constants
// ---------------------------------------------------------------------------
#define N_EXPERTS 30
#define IN_SZ     1024
#define HID       2048
#define BATCH_SZ  8192

#define N_CLUSTERS 74            // 148 CTAs / 2
#define N_WORK     960           // 32 m-blocks(256) x 30 experts, m-major

// Exact power-of-2 operand scaling (folded out in epilogue)
#define X_SCALE   64.0f          // 2^6:  |x|max ~5.4 -> ~350 < 448
#define W_SCALE   8192.0f        // 2^13: |w|max 1/32 -> 256 < 448
#define INV_SCALE 1.9073486328125e-6f   // 2^-19 exact

// ---------------------------------------------------------------------------
// Device scratch (fp8 e4m3 blobs, SW128-swizzled SMEM images).
// g_xa: A blob(mb128, kc8) = 16KB: x rows [mb*128,+128), k [kc*128,+128).
// g_wb: B blob(e, nt8, rank, kc8) = 16KB: 128 n-rows x 128B where
//       hid = nt*256 + rank*128 + row, k [kc*128,+128).
// ---------------------------------------------------------------------------
__device__ __align__(16) uint8_t g_xa[(size_t)BATCH_SZ * IN_SZ];                 // 8 MB
__device__ __align__(16) uint8_t g_wb[(size_t)N_EXPERTS * HID * IN_SZ];          // 63 MB
__device__ float g_zbuf[(size_t)N_EXPERTS * BATCH_SZ];                            // 1 MB

// ---------------------------------------------------------------------------
// PTX helpers
// ---------------------------------------------------------------------------
__device__ __forceinline__ uint32_t smem_to_u32(const void* p) {
    uint32_t a;
    asm("{ .reg .u64 t; cvta.to.shared.u64 t, %1; cvt.u32.u64 %0, t; }"
        : "=r"(a) : "l"(p));
    return a;
}

__device__ __forceinline__ uint32_t elect_one_pred() {
    uint32_t pred;
    asm volatile(
        "{\n\t.reg .pred p;\n\telect.sync _|p, 0xFFFFFFFF;\n\tselp.b32 %0, 1, 0, p;\n\t}"
        : "=r"(pred));
    return pred;
}

__device__ __forceinline__ uint32_t cluster_rank() {
    uint32_t r;
    asm("mov.u32 %0, %%cluster_ctarank;" : "=r"(r));
    return r;
}

#define MBARRIER_INIT(addr, cnt) \
    asm volatile("mbarrier.init.shared.b64 [%0], %1;" :: "r"((uint32_t)(addr)), "r"((uint32_t)(cnt)) : "memory")

#define MBARRIER_EXPECT_TX(addr, bytes) \
    asm volatile("mbarrier.arrive.expect_tx.shared.b64 _, [%0], %1;" \
        :: "r"((uint32_t)(addr)), "r"((uint32_t)(bytes)) : "memory")

// local wait, acquire at cta scope
#define MBARRIER_WAIT_PARITY(mbar_smem_addr, phase_parity) do { \
    uint32_t _mbar = (uint32_t)(mbar_smem_addr); \
    uint32_t _parity = (uint32_t)(phase_parity); \
    uint32_t _done; \
    asm volatile( \
        "{\n\t.reg .pred p;\n\t" \
        "mbarrier.try_wait.parity.acquire.cta.shared::cta.b64 p, [%1], %2;\n\t" \
        "selp.b32 %0, 1, 0, p;\n\t}" \
        : "=r"(_done) : "r"(_mbar), "r"(_parity) : "memory"); \
    if (!_done) { \
        asm volatile( \
            "{\n\t.reg .pred P1;\n\t" \
            "WAIT_LOOP_%=:\n\t" \
            "mbarrier.try_wait.parity.acquire.cta.shared::cta.b64 P1, [%0], %1, 0x989680;\n\t" \
            "@P1 bra.uni WAIT_DONE_%=;\n\t" \
            "bra.uni WAIT_LOOP_%=;\n\t" \
            "WAIT_DONE_%=:\n\t}" \
            :: "r"(_mbar), "r"(_parity) : "memory"); \
    } \
} while (0)

// cluster-scope acquire wait (peer-signaled barriers / peer data)
#define MBARRIER_WAIT_PARITY_CLU(mbar_smem_addr, phase_parity) do { \
    uint32_t _mbar = (uint32_t)(mbar_smem_addr); \
    uint32_t _parity = (uint32_t)(phase_parity); \
    uint32_t _done; \
    asm volatile( \
        "{\n\t.reg .pred p;\n\t" \
        "mbarrier.try_wait.parity.acquire.cluster.shared::cta.b64 p, [%1], %2;\n\t" \
        "selp.b32 %0, 1, 0, p;\n\t}" \
        : "=r"(_done) : "r"(_mbar), "r"(_parity) : "memory"); \
    if (!_done) { \
        asm volatile( \
            "{\n\t.reg .pred P1;\n\t" \
            "WAIT_LOOP_%=:\n\t" \
            "mbarrier.try_wait.parity.acquire.cluster.shared::cta.b64 P1, [%0], %1, 0x989680;\n\t" \
            "@P1 bra.uni WAIT_DONE_%=;\n\t" \
            "bra.uni WAIT_LOOP_%=;\n\t" \
            "WAIT_DONE_%=:\n\t}" \
            :: "r"(_mbar), "r"(_parity) : "memory"); \
    } \
} while (0)

// arrive on the same-offset mbarrier in cluster rank 0
#define MBARRIER_ARRIVE_RANK0(local_mbar_addr) \
    asm volatile( \
        "{\n\t.reg .b32 remAddr32;\n\t" \
        "mapa.shared::cluster.u32 remAddr32, %0, 0;\n\t" \
        "mbarrier.arrive.shared::cluster.b64 _, [remAddr32];\n\t}" \
        :: "r"((uint32_t)(local_mbar_addr)) : "memory")

#define CLUSTER_SYNC() do { \
    asm volatile("barrier.cluster.arrive.aligned;" ::: "memory"); \
    asm volatile("barrier.cluster.wait.aligned;" ::: "memory"); \
} while (0)

#define NAMED_BAR(id, cnt) \
    asm volatile("bar.sync %0, %1;" :: "r"(id), "r"(cnt) : "memory")

// bulk async copy global -> own-CTA shared, completion on LOCAL mbarrier
#define CP_BULK_G2S(dst_smem, src_gmem, bytes, mbar) \
    asm volatile("cp.async.bulk.shared::cluster.global.mbarrier::complete_tx::bytes " \
                 "[%0], [%1], %2, [%3];" \
        :: "r"((uint32_t)(dst_smem)), "l"(src_gmem), "r"((uint32_t)(bytes)), \
           "r"((uint32_t)(mbar)) : "memory")

// pack two floats to e4m3x2
__device__ __forceinline__ uint16_t f2e4m3x2(float lo, float hi) {
    uint16_t r;
    asm("cvt.rn.satfinite.e4m3x2.f32 %0, %1, %2;" : "=h"(r) : "f"(hi), "f"(lo));
    return r;
}

#if TC_OK
#define TCGEN05_ALLOC_CG2(smem_result_addr, nCols) \
    asm volatile("tcgen05.alloc.cta_group::2.sync.aligned.shared::cta.b32 [%0], %1;" \
        :: "r"((uint32_t)(smem_result_addr)), "r"((uint32_t)(nCols)) : "memory")

#define TCGEN05_DEALLOC_CG2(tmem_addr, nCols) \
    asm volatile("tcgen05.dealloc.cta_group::2.sync.aligned.b32 %0, %1;" \
        :: "r"(tmem_addr), "r"((uint32_t)(nCols)))

#define TCGEN05_RELINQUISH_CG2() \
    asm volatile("tcgen05.relinquish_alloc_permit.cta_group::2.sync.aligned;")

#define TCGEN05_COMMIT_MC_CG2(mbar_smem_addr, cta_mask) \
    asm volatile("tcgen05.commit.cta_group::2.mbarrier::arrive::one.shared::cluster.multicast::cluster.b64 [%0], %1;" \
        :: "r"((uint32_t)(mbar_smem_addr)), "h"((uint16_t)(cta_mask)) : "memory")

#define TCGEN05_WAIT_LD()  asm volatile("tcgen05.wait::ld.sync.aligned;" ::: "memory")
#define TCGEN05_FENCE_BEFORE() asm volatile("tcgen05.fence::before_thread_sync;" ::: "memory")
#define TCGEN05_FENCE_AFTER()  asm volatile("tcgen05.fence::after_thread_sync;" ::: "memory")

#define TCGEN05_LD_32X32B_X32(r, tmem_addr) \
    asm volatile( \
        "tcgen05.ld.sync.aligned.32x32b.x32.b32 " \
        "{%0, %1, %2, %3, %4, %5, %6, %7, " \
        " %8, %9, %10, %11, %12, %13, %14, %15, " \
        " %16, %17, %18, %19, %20, %21, %22, %23, " \
        " %24, %25, %26, %27, %28, %29, %30, %31}, [%32];" \
        : "=r"((r)[0]),  "=r"((r)[1]),  "=r"((r)[2]),  "=r"((r)[3]), \
          "=r"((r)[4]),  "=r"((r)[5]),  "=r"((r)[6]),  "=r"((r)[7]), \
          "=r"((r)[8]),  "=r"((r)[9]),  "=r"((r)[10]), "=r"((r)[11]), \
          "=r"((r)[12]), "=r"((r)[13]), "=r"((r)[14]), "=r"((r)[15]), \
          "=r"((r)[16]), "=r"((r)[17]), "=r"((r)[18]), "=r"((r)[19]), \
          "=r"((r)[20]), "=r"((r)[21]), "=r"((r)[22]), "=r"((r)[23]), \
          "=r"((r)[24]), "=r"((r)[25]), "=r"((r)[26]), "=r"((r)[27]), \
          "=r"((r)[28]), "=r"((r)[29]), "=r"((r)[30]), "=r"((r)[31]) \
        : "r"(tmem_addr))

// SW128 K-major SMEM descriptor (layout=SW128, Blackwell version=1, LBO=1, SBO=64)
static constexpr uint64_t SMEM_DESC_BASE_SW128 =
    (uint64_t(2) << 61) | (uint64_t(1) << 46) | (uint64_t(64) << 32) | (uint64_t(1) << 16);
#define MAKE_SMEM_DESC(base_addr) \
    (SMEM_DESC_BASE_SW128 | ((uint64_t)((base_addr) >> 4) & 0x3FFF))

// idesc for cta_group::2 kind::f8f6f4: dtype=F32(bit4), E4M3 a/b, N=256, M=256
static constexpr uint32_t IDESC_F8 =
    (1u << 4) | ((256u / 8) << 17) | ((256u / 16) << 24);

// cg2 fp8 SS MMA, fp32 D, no scales
__device__ __forceinline__ void mma_f8_ss_cg2(uint32_t d, uint64_t ad, uint64_t bd,
                                              uint32_t idesc, uint32_t acc) {
    asm volatile(
        "{\n\t.reg .pred p;\n\tsetp.ne.u32 p, %5, 0;\n\t"
        "tcgen05.mma.cta_group::2.kind::f8f6f4 [%0], %1, %2, %3, "
        "{%4, %4, %4, %4, %4, %4, %4, %4}, p;\n\t}"
        :: "r"(d), "l"(ad), "l"(bd), "r"(idesc), "r"(0u), "r"(acc) : "memory");
}
#endif  // TC_OK

// ---------------------------------------------------------------------------
// Persistent cg2 FP8 GEMM: A-resident with CROSS-ITEM A REUSE + D ping-pong.
// Work items in m-major order (wk = mb2*30 + e); each cluster takes a
// CONTIGUOUS range -> consecutive items share A (same mb2), so A reloads
// happen at most twice per cluster and most item boundaries are seamless.
// A-barrier parities keyed to an A-load counter, derived identically on
// producer and issue lanes. Flat B-chunk/tile parities unchanged from R16.
// 192 threads: w0-3 epilogue, w4 producer lane, w5 MMA-issue lane (rank0).
// ---------------------------------------------------------------------------
static constexpr int TILE_N   = 256;
static constexpr int STAGES   = 4;

static constexpr uint32_t S_TMEM   = 0;
static constexpr uint32_t S_AFULLL = 16;                 // per CTA, tx 128KB
static constexpr uint32_t S_AFULLC = 24;                 // rank0, cnt=2
static constexpr uint32_t S_AEMPTY = 32;                 // per CTA (commit-mc)
static constexpr uint32_t S_FULLL  = 40;                 // 4 x 8B per CTA (tx 16KB)
static constexpr uint32_t S_FULLC  = 72;                 // 4 x 8B rank0 (cnt=2)
static constexpr uint32_t S_EMPTY  = 104;                // 4 x 8B per CTA (cnt=1)
static constexpr uint32_t S_DONE0  = 136;                // per CTA (commit-mc)
static constexpr uint32_t S_DONE1  = 144;
static constexpr uint32_t S_EDONE0 = 152;                // rank0, cnt=2
static constexpr uint32_t S_EDONE1 = 160;
static constexpr uint32_t S_B1     = 1024;
static constexpr uint32_t S_W2     = 1024 + 4 * HID;         // 9216
static constexpr uint32_t S_A      = S_W2 + 4 * HID;         // 17408 (1024-aligned)
static constexpr uint32_t A_BYTES  = 131072;                 // 128 rows x 1024 k fp8
static constexpr uint32_t S_B      = S_A + A_BYTES;          // 148480
static constexpr uint32_t B_STAGE_BYTES = 16384;             // 128 n-rows x 128 B
static constexpr uint32_t SMEM_BYTES = S_B + STAGES * B_STAGE_BYTES; // 214016

__global__ void __launch_bounds__(192, 1) __cluster_dims__(2, 1, 1)
gemm_fused(const float* __restrict__ b1, const float* __restrict__ W2) {
#if TC_OK
    extern __shared__ __align__(1024) uint8_t smem[];
    const uint32_t sb = smem_to_u32(smem);
    const int tid  = threadIdx.x;
    const int wid  = tid >> 5;
    const uint32_t rank = cluster_rank();
    const int cid  = blockIdx.x >> 1;              // cluster id 0..73

    // contiguous m-major work range [wlo, whi)
    const int wlo = (cid * N_WORK) / N_CLUSTERS;
    const int whi = ((cid + 1) * N_WORK) / N_CLUSTERS;
    const int nwork = whi - wlo;                   // 12 or 13
    const int KKT   = nwork * 64;                  // total B chunks, flat
    const int NTT   = nwork * 8;                   // total 256-col tiles, flat

    if (wid == 0) TCGEN05_ALLOC_CG2(sb + S_TMEM, 512);
    if (tid == 0) {
        if (rank == 0) {
            MBARRIER_INIT(sb + S_AFULLC, 2);
            for (int s = 0; s < STAGES; s++) MBARRIER_INIT(sb + S_FULLC + 8 * s, 2);
            MBARRIER_INIT(sb + S_EDONE0, 2);
            MBARRIER_INIT(sb + S_EDONE1, 2);
        }
        MBARRIER_INIT(sb + S_AFULLL, 1);
        MBARRIER_INIT(sb + S_AEMPTY, 1);
        for (int s = 0; s < STAGES; s++) {
            MBARRIER_INIT(sb + S_FULLL + 8 * s, 1);   // expect_tx arms each phase
            MBARRIER_INIT(sb + S_EMPTY + 8 * s, 1);
        }
        MBARRIER_INIT(sb + S_DONE0, 1);
        MBARRIER_INIT(sb + S_DONE1, 1);
    }
    __syncthreads();

    uint32_t tmem;
    asm volatile("ld.shared.b32 %0, [%1];" : "=r"(tmem) : "r"(sb + S_TMEM));

    float* s_b1 = (float*)(smem + S_B1);
    float* s_w2 = (float*)(smem + S_W2);
    if (tid < 128) {
        const int e0 = wlo % N_EXPERTS;
        for (int i = tid; i < HID; i += 128) {
            s_b1[i] = __ldg(b1 + (size_t)e0 * HID + i);
            s_w2[i] = __ldg(W2 + (size_t)e0 * HID + i);
        }
    }
    __syncthreads();
    CLUSTER_SYNC();   // barriers ready cluster-wide before any arrival/tx

    if (wid == 4) {
        // =================== PRODUCER LANE (both CTAs) ===================
        if (elect_one_pred()) {
            const char* xa = (const char*)g_xa;
            const char* wb = (const char*)g_wb;
            int acnt = 0;   // A loads performed so far

            for (int w = 0; w < nwork; w++) {
                const int wkp = wlo + w;
                const int e_w = wkp % N_EXPERTS;
                const int mb2 = wkp / N_EXPERTS;            // m-block of 256
                const int mb  = mb2 * 2 + (int)rank;        // m-block of 128
                const bool ach = (w == 0) || (wkp % N_EXPERTS == 0);

                // ---- item boundary: FLUSH pending relay first (always) ----
                if (w >= 1) {
                    const int p = w * 64 - 1;     // last chunk of previous item
                    MBARRIER_WAIT_PARITY(sb + S_FULLL + 8 * (p & 3), (p >> 2) & 1);
                    MBARRIER_ARRIVE_RANK0(sb + S_FULLC + 8 * (p & 3));
                    if (ach)                      // drain MMAs only if A changes
                        MBARRIER_WAIT_PARITY(sb + S_AEMPTY, (acnt - 1) & 1);
                }

                // ---- A: load only when m-block changes ----
                if (ach) {
                    MBARRIER_EXPECT_TX(sb + S_AFULLL, A_BYTES);
                    const char* asrc = xa + ((size_t)mb << 17);
#pragma unroll
                    for (int kc = 0; kc < 8; kc++)
                        CP_BULK_G2S(sb + S_A + (uint32_t)kc * 16384u,
                                    asrc + ((size_t)kc << 14), 16384, sb + S_AFULLL);
                    acnt++;
                }

                // ---- B: 64 chunks of 16KB through the ring ----
                for (int j = 0; j < 64; j++) {
                    const int la = w * 64 + j;
                    const int s  = la & 3;
                    const int u  = la >> 2;
                    if (u >= 1)
                        MBARRIER_WAIT_PARITY(sb + S_EMPTY + 8 * s, (u - 1) & 1);

                    const int nt = j >> 3;        // N-tile of 256
                    const int kc = j & 7;         // K-chunk of 128
                    MBARRIER_EXPECT_TX(sb + S_FULLL + 8 * s, B_STAGE_BYTES);
                    const size_t boff =
                        ((size_t)(e_w * 128 + nt * 16 + (int)rank * 8 + kc)) << 14;
                    CP_BULK_G2S(sb + S_B + (uint32_t)s * B_STAGE_BYTES,
                                wb + boff, B_STAGE_BYTES, sb + S_FULLL + 8 * s);

                    // relay previous B chunk (within-item; j==0 handled at boundary)
                    if (j >= 1) {
                        const int p = la - 1;
                        MBARRIER_WAIT_PARITY(sb + S_FULLL + 8 * (p & 3), (p >> 2) & 1);
                        MBARRIER_ARRIVE_RANK0(sb + S_FULLC + 8 * (p & 3));
                    }
                    // relay A completion once per A load, early in the item
                    if (j == 1 && ach) {
                        MBARRIER_WAIT_PARITY(sb + S_AFULLL, (acnt - 1) & 1);
                        MBARRIER_ARRIVE_RANK0(sb + S_AFULLC);
                    }
                }
            }
            // relay final B chunk
            const int p = KKT - 1;
            MBARRIER_WAIT_PARITY(sb + S_FULLL + 8 * (p & 3), (p >> 2) & 1);
            MBARRIER_ARRIVE_RANK0(sb + S_FULLC + 8 * (p & 3));
        }
    } else if (wid == 5) {
        // =================== MMA ISSUE LANE (rank 0 only) ===================
        if (rank == 0 && elect_one_pred()) {
            int acnt = 0;
            for (int w = 0; w < nwork; w++) {
                const int wkp = wlo + w;
                const bool ach   = (w == 0) || (wkp % N_EXPERTS == 0);
                const bool glast = (w == nwork - 1) || ((wkp + 1) % N_EXPERTS == 0);
                if (ach) {
                    acnt++;
                    MBARRIER_WAIT_PARITY_CLU(sb + S_AFULLC, (acnt - 1) & 1);
                }
                for (int tile = 0; tile < 8; tile++) {
                    const int tt  = w * 8 + tile;
                    const int buf = tt & 1;
                    const uint32_t dbase = tmem + (uint32_t)buf * 256;
                    if (tt >= 2)                  // buffer reuse: epilogue done
                        MBARRIER_WAIT_PARITY_CLU(sb + (buf ? S_EDONE1 : S_EDONE0),
                                                 ((tt >> 1) - 1) & 1);
                    for (int kc = 0; kc < 8; kc++) {
                        const int kb = tt * 8 + kc;
                        const int s  = kb & 3;
                        MBARRIER_WAIT_PARITY_CLU(sb + S_FULLC + 8 * s, (kb >> 2) & 1);
                        TCGEN05_FENCE_AFTER();
                        const uint64_t ad = MAKE_SMEM_DESC(sb + S_A + (uint32_t)kc * 16384u);
                        const uint64_t bd = MAKE_SMEM_DESC(sb + S_B + (uint32_t)s * B_STAGE_BYTES);
#pragma unroll
                        for (int ks = 0; ks < 4; ks++)     // 4 x K32 per 128-chunk
                            mma_f8_ss_cg2(dbase, ad + ks * 2, bd + ks * 2,
                                          IDESC_F8, (uint32_t)((kc | ks) != 0));
                        TCGEN05_COMMIT_MC_CG2(sb + S_EMPTY + 8 * s, 0x3);
                    }
                    TCGEN05_COMMIT_MC_CG2(sb + (buf ? S_DONE1 : S_DONE0), 0x3);
                }
                if (glast)
                    TCGEN05_COMMIT_MC_CG2(sb + S_AEMPTY, 0x3);   // A group done
            }
        }
    } else {
        // =================== EPILOGUE WARPS (0-3) ===================
        float zacc[4] = {0.f, 0.f, 0.f, 0.f};

        for (int tt = 0; tt < NTT; tt++) {
            const int buf = tt & 1;
            const uint32_t dbase = tmem + (uint32_t)buf * 256;
            MBARRIER_WAIT_PARITY(sb + (buf ? S_DONE1 : S_DONE0), (tt >> 1) & 1);
            TCGEN05_FENCE_AFTER();

            uint32_t bufA[32], bufB[32];
            TCGEN05_LD_32X32B_X32(bufA, dbase);
            TCGEN05_WAIT_LD();
#pragma unroll
            for (int ch = 0; ch < 8; ch++) {
                if (ch < 7) {          // prefetch next chunk while consuming current
                    if (ch & 1) { TCGEN05_LD_32X32B_X32(bufA, dbase + (ch + 1) * 32); }
                    else        { TCGEN05_LD_32X32B_X32(bufB, dbase + (ch + 1) * 32); }
                }
                const uint32_t* cur = (ch & 1) ? bufB : bufA;
                const int nb = (tt & 7) * TILE_N + ch * 32;
#pragma unroll
                for (int c = 0; c < 32; c++) {
                    float h = fmaf(__uint_as_float(cur[c]), INV_SCALE, s_b1[nb + c]);
                    h = fmaxf(h, 0.f);
                    zacc[c & 3] = fmaf(h, s_w2[nb + c], zacc[c & 3]);
                }
                if (ch < 7) TCGEN05_WAIT_LD();
            }
            TCGEN05_FENCE_BEFORE();
            NAMED_BAR(2, 128);          // all 4 epilogue warps done with this buf
            if (tid == 0) MBARRIER_ARRIVE_RANK0(sb + (buf ? S_EDONE1 : S_EDONE0));

            if ((tt & 7) == 7) {
                // ---- end of work item: emit z, reset, load next b1/W2 ----
                const int w   = tt >> 3;
                const int wkp = wlo + w;
                const int e_w = wkp % N_EXPERTS;
                const int m0w = (wkp / N_EXPERTS) * 256 + (int)rank * 128;
                const float z = (zacc[0] + zacc[1]) + (zacc[2] + zacc[3]);
                g_zbuf[(size_t)e_w * BATCH_SZ + m0w + tid] = z;
                zacc[0] = zacc[1] = zacc[2] = zacc[3] = 0.f;

                if (w + 1 < nwork) {
                    const int e_n = (wkp + 1) % N_EXPERTS;
                    for (int i = tid; i < HID; i += 128) {
                        s_b1[i] = __ldg(b1 + (size_t)e_n * HID + i);
                        s_w2[i] = __ldg(W2 + (size_t)e_n * HID + i);
                    }
                }
                NAMED_BAR(2, 128);      // reload visible before next epilogue
            }
        }
    }

    __syncthreads();
    if (wid == 0) {
        TCGEN05_RELINQUISH_CG2();
        TCGEN05_DEALLOC_CG2(tmem, 512);
    }
    CLUSTER_SYNC();   // peer MMAs/multicasts targeting our SMEM must be done
#endif  // TC_OK
}

// ---------------------------------------------------------------------------
// Host/device shared swizzle
// ---------------------------------------------------------------------------
__device__ __forceinline__ uint32_t swz128(uint32_t o) {
    return o ^ ((o >> 3) & 0x70);
}

// x fp32 [B][K] -> g_xa fp8 blobs (scaled by 2^6); 16 k per thread.
__global__ void cvt_x_kernel(const float* __restrict__ x) {
    const int i = blockIdx.x * blockDim.x + threadIdx.x;   // < 8192*64
    const int m = i >> 6;
    const int g = i & 63;               // 16B group; kc = g>>3
    const float* src = x + (size_t)m * IN_SZ + g * 16;
    float v[16];
#pragma unroll
    for (int j = 0; j < 16; j++) v[j] = src[j] * X_SCALE;
    uint32_t w[4];
#pragma unroll
    for (int q = 0; q < 4; q++) {
        const uint16_t p01 = f2e4m3x2(v[4 * q + 0], v[4 * q + 1]);
        const uint16_t p23 = f2e4m3x2(v[4 * q + 2], v[4 * q + 3]);
        w[q] = (uint32_t)p01 | ((uint32_t)p23 << 16);
    }
    uint4 out = make_uint4(w[0], w[1], w[2], w[3]);
    const int mb = m >> 7, r = m & 127, kc = g >> 3;
    const uint32_t off = swz128((uint32_t)(r * 128 + (g & 7) * 16));
    *(uint4*)((char*)g_xa + (((size_t)(mb * 8 + kc)) << 14) + off) = out;
}

// W1 fp32 [E][K][H] -> g_wb fp8 16KB blobs (scaled by 2^13), K-major.
// blob(e, nt8, rank, kc8): row = hid&127, rank=(hid>>7)&1, nt=hid>>8.
__global__ void cvt_w1_kernel(const float* __restrict__ W1) {
    __shared__ float tile[128][33];
    const int e  = blockIdx.z;
    const int kc = blockIdx.y;          // K-chunk of 128
    const int hb = blockIdx.x;          // hid block of 32
    const int t  = threadIdx.x;         // 0..255
    const float* src = W1 + ((size_t)e * IN_SZ + kc * 128) * HID + hb * 32;
#pragma unroll
    for (int it = 0; it < 16; it++) {
        const int lin = it * 256 + t;   // < 4096 = 128k x 32h
        const int kr = lin >> 5, hc = lin & 31;
        tile[kr][hc] = src[(size_t)kr * HID + hc];
    }
    __syncthreads();
    const int h = t >> 3, g = t & 7;    // h: 0..31, g: 16B group 0..7
    float v[16];
#pragma unroll
    for (int j = 0; j < 16; j++) v[j] = tile[g * 16 + j][h] * W_SCALE;
    uint32_t w[4];
#pragma unroll
    for (int q = 0; q < 4; q++) {
        const uint16_t p01 = f2e4m3x2(v[4 * q + 0], v[4 * q + 1]);
        const uint16_t p23 = f2e4m3x2(v[4 * q + 2], v[4 * q + 3]);
        w[q] = (uint32_t)p01 | ((uint32_t)p23 << 16);
    }
    uint4 out = make_uint4(w[0], w[1], w[2], w[3]);
    const int hid = hb * 32 + h;
    const int nt  = hid >> 8;           // 256-col N tile
    const int rk  = (hid >> 7) & 1;
    const int row = hid & 127;
    const size_t blob = (size_t)(e * 128 + nt * 16 + rk * 8 + kc);
    const uint32_t off = swz128((uint32_t)(row * 128 + g * 16));
    *(uint4*)((char*)g_wb + (blob << 14) + off) = out;
}

// ---------------------------------------------------------------------------
// Final reduce: out[m] = mean_e sigmoid(z[e][m] + b2[e]); 4 threads/output
// ---------------------------------------------------------------------------
__global__ void reduce_kernel(const float* __restrict__ b2, float* __restrict__ out) {
    const int tid = blockIdx.x * blockDim.x + threadIdx.x;  // < 32768
    const int i = tid >> 2, l = tid & 3;
    float s = 0.f;
#pragma unroll
    for (int ex = l; ex < N_EXPERTS; ex += 4) {
        const float z = g_zbuf[(size_t)ex * BATCH_SZ + i] + b2[ex];
        s += 1.f / (1.f + __expf(-z));
    }
    s += __shfl_xor_sync(0xFFFFFFFFu, s, 1);
    s += __shfl_xor_sync(0xFFFFFFFFu, s, 2);
    if (l == 0) out[i] = s * (1.f / N_EXPERTS);
}

// ---------------------------------------------------------------------------
// Harness entry
// ---------------------------------------------------------------------------
extern "C" void kernel_launch(void* const* d_in, const int* in_sizes, int n_in,
                              void* d_out, int out_size) {
    (void)in_sizes; (void)n_in; (void)out_size;
    const float* x  = (const float*)d_in[0];
    const float* W1 = (const float*)d_in[1];
    const float* b1 = (const float*)d_in[2];
    const float* W2 = (const float*)d_in[3];
    const float* b2 = (const float*)d_in[4];
    float* out = (float*)d_out;

    cudaFuncSetAttribute(gemm_fused, cudaFuncAttributeMaxDynamicSharedMemorySize,
                         (int)SMEM_BYTES);

    cvt_x_kernel<<<(BATCH_SZ * 64) / 256, 256>>>(x);

    dim3 tg(HID / 32, IN_SZ / 128, N_EXPERTS);   // (hb, kc, e)
    cvt_w1_kernel<<<tg, 256>>>(W1);

    // persistent: 148 CTAs = 74 cg2 clusters
    gemm_fused<<<2 * N_CLUSTERS, 192, SMEM_BYTES>>>(b1, W2);

    reduce_kernel<<<(BATCH_SZ * 4) / 256, 256>>>(b2, out);
}